// round 13
// baseline (speedup 1.0000x reference)
#include <cuda_runtime.h>
#include <cuda_fp16.h>
#include <math.h>
#include <stdint.h>

#define N_NODES 10000
#define E_EDGES 160000
#define DCH 512
#define C_HEAD 256
#define HEADS 2
#define TDIM 128
#define MDIM 256
#define FDIM 384   // TDIM + MDIM
#define NCAT 2816  // 4*512 (q,k,v,skip) + 2*384 (p heads)

// ---------------- scratch (device globals) ----------------
__device__ float  g_q[N_NODES * DCH];
__device__ float  g_k[N_NODES * DCH];
__device__ float  g_v[N_NODES * DCH];
__device__ float  g_p[N_NODES * HEADS * FDIM];
__device__ float  g_WeT[HEADS * C_HEAD * FDIM];       // WeT[h][c][f] = We[f][h*C+c]
__device__ float  g_pbias[HEADS * FDIM];
__device__ int    g_deg[N_NODES];
__device__ int    g_cur[N_NODES];
__device__ int    g_off[N_NODES + 1];
__device__ int    g_perm[E_EDGES];
// fp16 operands: A-side split (hi+lo), B-side single
__device__ __half g_xhi[N_NODES * DCH];
__device__ __half g_xlo[N_NODES * DCH];
__device__ __half g_w[NCAT * DCH];                     // K-major: [n][k], single fp16
__device__ __half g_wekt[HEADS * C_HEAD * FDIM];       // [h][n][k] single fp16
__device__ __half g_ghi[N_NODES * HEADS * FDIM];       // [n][h*384+f]
__device__ __half g_glo[N_NODES * HEADS * FDIM];

// ================= mma.sync helpers (fp16 in, fp32 accum) =================
__device__ __forceinline__ void mma_f16_acc(
    float c[4], uint32_t a0, uint32_t a1, uint32_t a2, uint32_t a3,
    uint32_t b0, uint32_t b1)
{
    asm volatile(
        "mma.sync.aligned.m16n8k16.row.col.f32.f16.f16.f32 "
        "{%0,%1,%2,%3}, {%4,%5,%6,%7}, {%8,%9}, {%0,%1,%2,%3};"
        : "+f"(c[0]), "+f"(c[1]), "+f"(c[2]), "+f"(c[3])
        : "r"(a0), "r"(a1), "r"(a2), "r"(a3), "r"(b0), "r"(b1));
}
__device__ __forceinline__ void ldm_x4(uint32_t& r0, uint32_t& r1,
                                       uint32_t& r2, uint32_t& r3, uint32_t a) {
    asm volatile("ldmatrix.sync.aligned.m8n8.x4.shared.b16 {%0,%1,%2,%3}, [%4];"
                 : "=r"(r0), "=r"(r1), "=r"(r2), "=r"(r3) : "r"(a));
}

#define LDK 24                       // 48B row stride: 16B-aligned, ldmatrix conflict-free
#define STG_ELEMS (128 * LDK)        // 3072 fp16 = 6144 B per array
#define AR_BYTES (STG_ELEMS * 2)
#define ST_BYTES (3 * AR_BYTES)      // Ah, Al, B = 18432 B per stage

// ---------------- mma mainloop: 128x128 CTA tile, BK=16, double-buffered -------
// 256 threads, 8 warps, warp tile 32x64 (4m x 2n grid). 2-product split-fp16.
__device__ __forceinline__ void mma_mainloop(
    const __half* __restrict__ Ahi, const __half* __restrict__ Alo,
    int lda, int m0, int Mrows,
    const __half* __restrict__ B, int ldb, int n0, int K,
    float cacc[2][8][4])
{
    __shared__ __align__(16) char smraw[2 * ST_BYTES];   // 36 KB static

    const int tid = threadIdx.x;
    const int row = tid >> 1;
    const int colh = (tid & 1) * 8;
    const int lane = tid & 31;
    const int wid = tid >> 5;
    const int wm = (wid & 3) * 32;
    const int wn = (wid >> 2) * 64;
    const int lr = lane & 7, seg = lane >> 3;

    const bool aOk = (m0 + row) < Mrows;
    const int arow = aOk ? (m0 + row) : 0;
    const __half* Aph = Ahi + (size_t)arow * lda + colh;
    const __half* Apl = Alo + (size_t)arow * lda + colh;
    const __half* Bp  = B + (size_t)(n0 + row) * ldb + colh;

    const uint32_t smBase = (uint32_t)__cvta_generic_to_shared(smraw);
    const uint32_t wrOff = (row * LDK + colh) * 2;

    const int nkt = K >> 4;

    uint32_t bOffP[4], aOffM[2];
#pragma unroll
    for (int p = 0; p < 4; p++)
        bOffP[p] = ((wn + (2 * p + (seg >> 1)) * 8 + lr) * LDK + (seg & 1) * 8) * 2;
#pragma unroll
    for (int mt = 0; mt < 2; mt++)
        aOffM[mt] = ((wm + mt * 16 + (seg & 1) * 8 + lr) * LDK + (seg >> 1) * 8) * 2;

    const uint4 z4 = make_uint4(0u, 0u, 0u, 0u);
    uint4 rah = aOk ? *(const uint4*)Aph : z4;
    uint4 ral = aOk ? *(const uint4*)Apl : z4;
    uint4 rb  = *(const uint4*)Bp;

    {
        char* b = smraw + wrOff;
        *(uint4*)(b + 0 * AR_BYTES) = rah;
        *(uint4*)(b + 1 * AR_BYTES) = ral;
        *(uint4*)(b + 2 * AR_BYTES) = rb;
    }
    __syncthreads();

    for (int kt = 0; kt < nkt; kt++) {
        const int s = kt & 1;
        if (kt + 1 < nkt) {
            const int ko = (kt + 1) * 16;
            rah = aOk ? *(const uint4*)(Aph + ko) : z4;
            ral = aOk ? *(const uint4*)(Apl + ko) : z4;
            rb  = *(const uint4*)(Bp + ko);
        }

        const uint32_t sb = smBase + s * ST_BYTES;
        uint32_t bh[8][2];
#pragma unroll
        for (int p = 0; p < 4; p++)
            ldm_x4(bh[2 * p][0], bh[2 * p][1], bh[2 * p + 1][0], bh[2 * p + 1][1],
                   sb + 2 * AR_BYTES + bOffP[p]);
#pragma unroll
        for (int mt = 0; mt < 2; mt++) {
            uint32_t ah0, ah1, ah2, ah3, al0, al1, al2, al3;
            ldm_x4(ah0, ah1, ah2, ah3, sb + 0 * AR_BYTES + aOffM[mt]);
            ldm_x4(al0, al1, al2, al3, sb + 1 * AR_BYTES + aOffM[mt]);
#pragma unroll
            for (int nt = 0; nt < 8; nt++) {
                mma_f16_acc(cacc[mt][nt], ah0, ah1, ah2, ah3, bh[nt][0], bh[nt][1]);
                mma_f16_acc(cacc[mt][nt], al0, al1, al2, al3, bh[nt][0], bh[nt][1]);
            }
        }

        if (kt + 1 < nkt) {
            char* b = smraw + (s ^ 1) * ST_BYTES + wrOff;
            *(uint4*)(b + 0 * AR_BYTES) = rah;
            *(uint4*)(b + 1 * AR_BYTES) = ral;
            *(uint4*)(b + 2 * AR_BYTES) = rb;
            __syncthreads();
        }
    }
}

// ---------------- kernel 1: fused projections q/k/v/skip/p ----------------
__global__ void __launch_bounds__(256, 2) mma_proj(
    const float* __restrict__ bq, const float* __restrict__ bk,
    const float* __restrict__ bv, const float* __restrict__ bs,
    float* __restrict__ out)
{
    float cacc[2][8][4] = {};
    const int j = blockIdx.x;
    const int m0 = blockIdx.y * 128;
    mma_mainloop(g_xhi, g_xlo, DCH, m0, N_NODES,
                 g_w, DCH, j * 128, DCH, cacc);

    const int lane = threadIdx.x & 31, wid = threadIdx.x >> 5;
    const int wm = (wid & 3) * 32, wn = (wid >> 2) * 64;
    const int g = lane >> 2, t = lane & 3;

    float* dst; const float* bvec; int col0, ldc;
    if (j < 16) {
        int seg = j >> 2;
        dst = (seg == 0) ? g_q : (seg == 1) ? g_k : (seg == 2) ? g_v : out;
        bvec = (seg == 0) ? bq : (seg == 1) ? bk : (seg == 2) ? bv : bs;
        col0 = (j & 3) * 128; ldc = DCH;
    } else {
        dst = g_p; bvec = g_pbias;
        col0 = (j - 16) * 128; ldc = HEADS * FDIM;
    }
#pragma unroll
    for (int mt = 0; mt < 2; mt++) {
#pragma unroll
        for (int nt = 0; nt < 8; nt++) {
            int gc = col0 + wn + nt * 8 + 2 * t;
            float b0v = bvec[gc], b1v = bvec[gc + 1];
            int r0 = m0 + wm + mt * 16 + g;
            if (r0 < N_NODES) {
                float2 v = make_float2(cacc[mt][nt][0] + b0v, cacc[mt][nt][1] + b1v);
                *(float2*)&dst[(size_t)r0 * ldc + gc] = v;
            }
            int r1 = r0 + 8;
            if (r1 < N_NODES) {
                float2 v = make_float2(cacc[mt][nt][2] + b0v, cacc[mt][nt][3] + b1v);
                *(float2*)&dst[(size_t)r1 * ldc + gc] = v;
            }
        }
    }
}

// ---------------- kernel 2: out += G @ We (per head) ----------------
__global__ void __launch_bounds__(256, 2) mma_out(float* __restrict__ out)
{
    float cacc[2][8][4] = {};
    const int j = blockIdx.x;
    const int h = j >> 1, jt = j & 1;
    const int m0 = blockIdx.y * 128;
    mma_mainloop(g_ghi + h * FDIM, g_glo + h * FDIM, HEADS * FDIM, m0, N_NODES,
                 g_wekt + (size_t)h * C_HEAD * FDIM, FDIM, jt * 128, FDIM, cacc);

    const int lane = threadIdx.x & 31, wid = threadIdx.x >> 5;
    const int wm = (wid & 3) * 32, wn = (wid >> 2) * 64;
    const int g = lane >> 2, t = lane & 3;
    const int col0 = h * C_HEAD + jt * 128;

#pragma unroll
    for (int mt = 0; mt < 2; mt++) {
#pragma unroll
        for (int nt = 0; nt < 8; nt++) {
            int gc = col0 + wn + nt * 8 + 2 * t;
            int r0 = m0 + wm + mt * 16 + g;
            if (r0 < N_NODES) {
                float2* op = (float2*)&out[(size_t)r0 * DCH + gc];
                float2 v = *op;
                v.x += cacc[mt][nt][0]; v.y += cacc[mt][nt][1];
                *op = v;
            }
            int r1 = r0 + 8;
            if (r1 < N_NODES) {
                float2* op = (float2*)&out[(size_t)r1 * DCH + gc];
                float2 v = *op;
                v.x += cacc[mt][nt][2]; v.y += cacc[mt][nt][3];
                *op = v;
            }
        }
    }
}

// ---------------- fp32 GEMM tile (M = Wq @ WeT, writes single fp16 weights) ------
__device__ __forceinline__ void gemm_tile_w(
    const float* __restrict__ A, int lda,
    const float* __restrict__ B, int ldb,
    int K, int bm, int bn,
    __half* wdst, int wrow0,
    float As[2][16][136], float Bs[2][16][128])
{
    const int tid = threadIdx.x;
    const int tx = tid & 15, ty = tid >> 4;
    const int aRow = tid >> 2;
    const int aCol = (tid & 3) * 4;
    const int bRow = tid >> 4;
    const int bCol = (tid & 15) * 4;

    const float* Ap0 = A + (size_t)(bm + aRow) * lda + aCol;
    const float* Ap1 = A + (size_t)(bm + aRow + 64) * lda + aCol;
    const float* Bp0 = B + (size_t)bRow * ldb + bn + bCol;
    const float* Bp1 = Bp0 + 64;
    const int nkt = K >> 4;

    float4 a0r = *(const float4*)Ap0;
    float4 a1r = *(const float4*)Ap1;
    float4 b0r = *(const float4*)Bp0;
    float4 b1r = *(const float4*)Bp1;

    As[0][aCol + 0][aRow] = a0r.x; As[0][aCol + 1][aRow] = a0r.y;
    As[0][aCol + 2][aRow] = a0r.z; As[0][aCol + 3][aRow] = a0r.w;
    As[0][aCol + 0][aRow + 64] = a1r.x; As[0][aCol + 1][aRow + 64] = a1r.y;
    As[0][aCol + 2][aRow + 64] = a1r.z; As[0][aCol + 3][aRow + 64] = a1r.w;
    *(float4*)&Bs[0][bRow][bCol] = b0r;
    *(float4*)&Bs[0][bRow][bCol + 64] = b1r;
    __syncthreads();

    float acc[8][8];
#pragma unroll
    for (int i = 0; i < 8; i++)
#pragma unroll
        for (int jj = 0; jj < 8; jj++) acc[i][jj] = 0.f;

    for (int kt = 0; kt < nkt; kt++) {
        const int s = kt & 1;
        if (kt + 1 < nkt) {
            const int ko = (kt + 1) * 16;
            a0r = *(const float4*)(Ap0 + ko);
            a1r = *(const float4*)(Ap1 + ko);
            b0r = *(const float4*)(Bp0 + (size_t)ko * ldb);
            b1r = *(const float4*)(Bp1 + (size_t)ko * ldb);
        }
#pragma unroll
        for (int kk = 0; kk < 16; kk++) {
            float4 av0 = *(const float4*)&As[s][kk][ty * 8];
            float4 av1 = *(const float4*)&As[s][kk][ty * 8 + 4];
            float4 bv0 = *(const float4*)&Bs[s][kk][tx * 4];
            float4 bv1 = *(const float4*)&Bs[s][kk][tx * 4 + 64];
            float ar[8] = {av0.x, av0.y, av0.z, av0.w, av1.x, av1.y, av1.z, av1.w};
            float br[8] = {bv0.x, bv0.y, bv0.z, bv0.w, bv1.x, bv1.y, bv1.z, bv1.w};
#pragma unroll
            for (int i = 0; i < 8; i++)
#pragma unroll
                for (int jj = 0; jj < 8; jj++) acc[i][jj] += ar[i] * br[jj];
        }
        if (kt + 1 < nkt) {
            __syncthreads();
            const int s1 = s ^ 1;
            As[s1][aCol + 0][aRow] = a0r.x; As[s1][aCol + 1][aRow] = a0r.y;
            As[s1][aCol + 2][aRow] = a0r.z; As[s1][aCol + 3][aRow] = a0r.w;
            As[s1][aCol + 0][aRow + 64] = a1r.x; As[s1][aCol + 1][aRow + 64] = a1r.y;
            As[s1][aCol + 2][aRow + 64] = a1r.z; As[s1][aCol + 3][aRow + 64] = a1r.w;
            *(float4*)&Bs[s1][bRow][bCol] = b0r;
            *(float4*)&Bs[s1][bRow][bCol + 64] = b1r;
            __syncthreads();
        }
    }

#pragma unroll
    for (int i = 0; i < 8; i++) {
        int kk = bm + ty * 8 + i;
#pragma unroll
        for (int jj = 0; jj < 8; jj++) {
            int f = bn + ((jj < 4) ? (tx * 4 + jj) : (64 + tx * 4 + jj - 4));
            int n = wrow0 + f;
            wdst[(size_t)n * DCH + kk] = __float2half_rn(acc[i][jj]);
        }
    }
}

__global__ void __launch_bounds__(256) gemm_m_kernel(const float* __restrict__ Wq) {
    __shared__ __align__(16) float As[2][16][136];
    __shared__ __align__(16) float Bs[2][16][128];
    int h = blockIdx.z;
    gemm_tile_w(Wq + h * C_HEAD, DCH,
                g_WeT + (size_t)h * C_HEAD * FDIM, FDIM,
                C_HEAD, blockIdx.y * 128, blockIdx.x * 128,
                g_w, 4 * DCH + h * FDIM, As, Bs);
}

// ---------------- prep: conv x (split), conv W (single), conv WeKT, pbias --------
#define PB_X  20000
#define PB_W  4096
#define PB_WE 768
#define PB_PB 3
__global__ void misc_prep(const float* __restrict__ x, const float* __restrict__ We,
                          const float* __restrict__ bq,
                          const float* __restrict__ Wq, const float* __restrict__ Wk,
                          const float* __restrict__ Wv, const float* __restrict__ Ws)
{
    int b = blockIdx.x, t = threadIdx.x;
    if (b < PB_X) {
        int i = b * 256 + t;
        float v = x[i];
        __half h = __float2half_rn(v);
        g_xhi[i] = h;
        g_xlo[i] = __float2half_rn(v - __half2float(h));
    } else if (b < PB_X + PB_W) {
        int idx = (b - PB_X) * 256 + t;
        int k = idx >> 11, n = idx & 2047;
        int seg = n >> 9, cc = n & 511;
        const float* W = (seg == 0) ? Wq : (seg == 1) ? Wk : (seg == 2) ? Wv : Ws;
        g_w[(size_t)n * DCH + k] = __float2half_rn(W[(size_t)k * DCH + cc]);
    } else if (b < PB_X + PB_W + PB_WE) {
        int idx = (b - PB_X - PB_W) * 256 + t;   // [h][n][k] with k fastest
        int h = idx / (C_HEAD * FDIM);
        int r = idx - h * (C_HEAD * FDIM);
        int n = r / FDIM, k = r - n * FDIM;
        g_wekt[idx] = __float2half_rn(We[(size_t)k * DCH + h * C_HEAD + n]);
    } else {
        int i = (b - PB_X - PB_W - PB_WE) * 256 + t;
        if (i < HEADS * FDIM) {
            int h = i / FDIM, f = i - h * FDIM;
            float s = 0.f;
            for (int c = 0; c < C_HEAD; c++)
                s += bq[h * C_HEAD + c] * We[(size_t)f * DCH + h * C_HEAD + c];
            g_pbias[i] = s;
        }
    }
}

// ---------------- We transpose ----------------
__global__ void transpose_we_kernel(const float* __restrict__ We) {
    int i = blockIdx.x * 256 + threadIdx.x;
    if (i < HEADS * C_HEAD * FDIM) {
        int h = i / (C_HEAD * FDIM);
        int r = i % (C_HEAD * FDIM);
        int c = r / FDIM;
        int f = r % FDIM;
        g_WeT[i] = We[(size_t)f * DCH + h * C_HEAD + c];
    }
}

// ---------------- CSR build ----------------
__global__ void zero_deg_kernel() {
    int i = blockIdx.x * 256 + threadIdx.x;
    if (i < N_NODES) g_deg[i] = 0;
}
__global__ void count_deg_kernel(const int* __restrict__ ei) {
    int i = blockIdx.x * 256 + threadIdx.x;
    if (i < E_EDGES) atomicAdd(&g_deg[ei[E_EDGES + i]], 1);
}
__global__ void __launch_bounds__(1024) scan_kernel() {
    __shared__ int part[1024];
    int tid = threadIdx.x;
    int base = tid * 10;
    int local[10];
    int s = 0;
#pragma unroll
    for (int j = 0; j < 10; j++) {
        int idx = base + j;
        int d = (idx < N_NODES) ? g_deg[idx] : 0;
        local[j] = d;
        s += d;
    }
    part[tid] = s;
    __syncthreads();
    for (int off = 1; off < 1024; off <<= 1) {
        int v = part[tid];
        int add = (tid >= off) ? part[tid - off] : 0;
        __syncthreads();
        part[tid] = v + add;
        __syncthreads();
    }
    int run = (tid > 0) ? part[tid - 1] : 0;
#pragma unroll
    for (int j = 0; j < 10; j++) {
        int idx = base + j;
        if (idx < N_NODES) {
            g_off[idx] = run;
            run += local[j];
            g_cur[idx] = 0;
        }
    }
    if (tid == 1023) g_off[N_NODES] = part[1023];
}
__global__ void scatter_perm_kernel(const int* __restrict__ ei) {
    int i = blockIdx.x * 256 + threadIdx.x;
    if (i < E_EDGES) {
        int d = ei[E_EDGES + i];
        int p = g_off[d] + atomicAdd(&g_cur[d], 1);
        g_perm[p] = i;
    }
}

// ---------------- fused edge logits + online softmax + aggregation ----------------
// Merged stage+logit phase (ea·p computed from load registers); v prefetch in accum.
#define CHUNK 12
__global__ void __launch_bounds__(128) fused_attn_kernel(
    const int* __restrict__ ei, const float* __restrict__ tfeat,
    const float* __restrict__ msg, float* __restrict__ out)
{
    const int n = blockIdx.x;
    const int tid = threadIdx.x;
    const int beg = g_off[n];
    const int deg = g_off[n + 1] - beg;

    if (deg == 0) {
        __half z = __float2half_rn(0.f);
#pragma unroll
        for (int l = 0; l < 3; l++) {
            size_t gi = (size_t)n * (HEADS * FDIM) + tid * 3 + l;
            g_ghi[gi] = z;        g_glo[gi] = z;
            g_ghi[gi + FDIM] = z; g_glo[gi + FDIM] = z;
        }
        return;
    }

    __shared__ __align__(16) float sq[DCH];
    __shared__ __align__(16) float sp[HEADS * FDIM];
    __shared__ __align__(16) float sea[CHUNK][FDIM];
    __shared__ float slog0[CHUNK], slog1[CHUNK];
    __shared__ float sw0[CHUNK], sw1[CHUNK];
    __shared__ int   ssrc[CHUNK];

    ((float4*)sq)[tid] = ((const float4*)(g_q + (size_t)n * DCH))[tid];
#pragma unroll
    for (int i = tid; i < (HEADS * FDIM) / 4; i += 128)
        ((float4*)sp)[i] = ((const float4*)(g_p + (size_t)n * (HEADS * FDIM)))[i];

    const int wid = tid >> 5, lane = tid & 31;

    float acc0 = 0.f, acc1 = 0.f, acc2 = 0.f, acc3 = 0.f;
    float ga0[3] = {0.f, 0.f, 0.f}, ga1[3] = {0.f, 0.f, 0.f};
    float rm0 = -1e30f, rm1 = -1e30f, den0 = 0.f, den1 = 0.f;

    for (int base = 0; base < deg; base += CHUNK) {
        const int cnt = min(CHUNK, deg - base);
        __syncthreads();   // protect sea/ssrc/sw reuse (also orders sq/sp on first iter)

        // merged phase a+b: stage edge_attr AND compute logits from load registers
        for (int j = wid; j < cnt; j += 4) {
            int e = g_perm[beg + base + j];
            int src = ei[e];                 // converged broadcast load
            if (lane == 0) ssrc[j] = src;
            const float4* tr4 = (const float4*)(tfeat + (size_t)e * TDIM);
            const float4* mr4 = (const float4*)(msg + (size_t)e * MDIM);
            float4 tv  = tr4[lane];
            float4 m0v = mr4[lane];
            float4 m1v = mr4[32 + lane];
            ((float4*)sea[j])[lane]      = tv;
            ((float4*)sea[j])[32 + lane] = m0v;
            ((float4*)sea[j])[64 + lane] = m1v;

            const float4* kr = (const float4*)(g_k + (size_t)src * DCH);
            float a0 = 0.f, a1 = 0.f;
#pragma unroll
            for (int it = 0; it < 2; it++) {
                float4 kv = kr[lane + 32 * it];
                float4 qv = ((const float4*)sq)[lane + 32 * it];
                a0 += kv.x * qv.x + kv.y * qv.y + kv.z * qv.z + kv.w * qv.w;
            }
#pragma unroll
            for (int it = 2; it < 4; it++) {
                float4 kv = kr[lane + 32 * it];
                float4 qv = ((const float4*)sq)[lane + 32 * it];
                a1 += kv.x * qv.x + kv.y * qv.y + kv.z * qv.z + kv.w * qv.w;
            }
            // ea . p from registers (three 128-float segments)
            {
                float4 p0 = ((const float4*)sp)[lane];
                float4 p1 = ((const float4*)sp)[96 + lane];
                a0 += tv.x * p0.x + tv.y * p0.y + tv.z * p0.z + tv.w * p0.w;
                a1 += tv.x * p1.x + tv.y * p1.y + tv.z * p1.z + tv.w * p1.w;
                p0 = ((const float4*)sp)[32 + lane];
                p1 = ((const float4*)sp)[128 + lane];
                a0 += m0v.x * p0.x + m0v.y * p0.y + m0v.z * p0.z + m0v.w * p0.w;
                a1 += m0v.x * p1.x + m0v.y * p1.y + m0v.z * p1.z + m0v.w * p1.w;
                p0 = ((const float4*)sp)[64 + lane];
                p1 = ((const float4*)sp)[160 + lane];
                a0 += m1v.x * p0.x + m1v.y * p0.y + m1v.z * p0.z + m1v.w * p0.w;
                a1 += m1v.x * p1.x + m1v.y * p1.y + m1v.z * p1.z + m1v.w * p1.w;
            }
#pragma unroll
            for (int o = 16; o; o >>= 1) {
                a0 += __shfl_xor_sync(0xffffffffu, a0, o);
                a1 += __shfl_xor_sync(0xffffffffu, a1, o);
            }
            if (lane == 0) {
                slog0[j] = a0 * 0.0625f;
                slog1[j] = a1 * 0.0625f;
            }
        }
        __syncthreads();

        // phase c: online-softmax rescale + chunk weights
        float cm0 = -1e30f, cm1 = -1e30f;
        for (int j = 0; j < cnt; j++) {
            cm0 = fmaxf(cm0, slog0[j]);
            cm1 = fmaxf(cm1, slog1[j]);
        }
        float nm0 = fmaxf(rm0, cm0), nm1 = fmaxf(rm1, cm1);
        float sc0 = expf(rm0 - nm0), sc1 = expf(rm1 - nm1);
        float scv = (tid < 64) ? sc0 : sc1;
        acc0 *= scv; acc1 *= scv; acc2 *= scv; acc3 *= scv;
#pragma unroll
        for (int l = 0; l < 3; l++) { ga0[l] *= sc0; ga1[l] *= sc1; }
        den0 *= sc0; den1 *= sc1;
        rm0 = nm0; rm1 = nm1;
        if (tid < cnt) {
            sw0[tid] = expf(slog0[tid] - nm0);
            sw1[tid] = expf(slog1[tid] - nm1);
        }
        __syncthreads();

        // phase d: accumulate v and G from staged chunk (v prefetched 1 deep)
        float4 vv = *(const float4*)(g_v + (size_t)ssrc[0] * DCH + tid * 4);
        for (int j = 0; j < cnt; j++) {
            float4 cur = vv;
            if (j + 1 < cnt)
                vv = *(const float4*)(g_v + (size_t)ssrc[j + 1] * DCH + tid * 4);
            float w0 = sw0[j], w1 = sw1[j];
            float wv = (tid < 64) ? w0 : w1;
            acc0 += wv * cur.x; acc1 += wv * cur.y;
            acc2 += wv * cur.z; acc3 += wv * cur.w;
            const float* er = sea[j] + tid * 3;
            float e0 = er[0], e1 = er[1], e2 = er[2];
            ga0[0] += w0 * e0; ga0[1] += w0 * e1; ga0[2] += w0 * e2;
            ga1[0] += w1 * e0; ga1[1] += w1 * e1; ga1[2] += w1 * e2;
            den0 += w0; den1 += w1;
        }
    }

    float inv0 = 1.f / (den0 + 1e-16f);
    float inv1 = 1.f / (den1 + 1e-16f);
    float invv = (tid < 64) ? inv0 : inv1;

    float4* op = (float4*)(out + (size_t)n * DCH + tid * 4);
    float4 o = *op;
    o.x += acc0 * invv; o.y += acc1 * invv;
    o.z += acc2 * invv; o.w += acc3 * invv;
    *op = o;

#pragma unroll
    for (int l = 0; l < 3; l++) {
        size_t gi = (size_t)n * (HEADS * FDIM) + tid * 3 + l;
        float v0 = ga0[l] * inv0;
        float v1 = ga1[l] * inv1;
        __half h0 = __float2half_rn(v0);
        __half h1 = __float2half_rn(v1);
        g_ghi[gi] = h0;
        g_glo[gi] = __float2half_rn(v0 - __half2float(h0));
        g_ghi[gi + FDIM] = h1;
        g_glo[gi + FDIM] = __float2half_rn(v1 - __half2float(h1));
    }
}

// ---------------- launch ----------------
extern "C" void kernel_launch(void* const* d_in, const int* in_sizes, int n_in,
                              void* d_out, int out_size)
{
    const float* x     = (const float*)d_in[0];
    const int*   ei    = (const int*)d_in[2];
    const float* tfeat = (const float*)d_in[3];
    const float* msg   = (const float*)d_in[4];
    const float* Wq    = (const float*)d_in[5];
    const float* bq    = (const float*)d_in[6];
    const float* Wk    = (const float*)d_in[7];
    const float* bk    = (const float*)d_in[8];
    const float* Wv    = (const float*)d_in[9];
    const float* bv    = (const float*)d_in[10];
    const float* We    = (const float*)d_in[11];
    const float* Ws    = (const float*)d_in[12];
    const float* bs    = (const float*)d_in[13];
    float* out = (float*)d_out;

    // 1: conversions + pbias
    misc_prep<<<PB_X + PB_W + PB_WE + PB_PB, 256>>>(x, We, bq, Wq, Wk, Wv, Ws);
    // 2: WeT (fp32, for M)
    transpose_we_kernel<<<(HEADS * C_HEAD * FDIM + 255) / 256, 256>>>(We);
    // 3: M_h = Wq_h @ WeT_h  (written as single fp16 into g_w rows 2048+)
    dim3 gm(FDIM / 128, 4, HEADS);
    gemm_m_kernel<<<gm, 256>>>(Wq);
    // 4: tensor-core projection GEMM  <-- profiled slot
    dim3 gproj(NCAT / 128, (N_NODES + 127) / 128);
    mma_proj<<<gproj, 256>>>(bq, bk, bv, bs, out);
    // 5-8: CSR
    zero_deg_kernel<<<(N_NODES + 255) / 256, 256>>>();
    count_deg_kernel<<<(E_EDGES + 255) / 256, 256>>>(ei);
    scan_kernel<<<1, 1024>>>();
    scatter_perm_kernel<<<(E_EDGES + 255) / 256, 256>>>(ei);
    // 9: fused edge logits + online softmax + aggregation
    fused_attn_kernel<<<N_NODES, 128>>>(ei, tfeat, msg, out);
    // 10: out += G @ We  (mma.sync, 2-product split-fp16)
    dim3 gout(2 * HEADS, (N_NODES + 127) / 128);
    mma_out<<<gout, 256>>>(out);
}

// round 14
// speedup vs baseline: 1.0760x; 1.0760x over previous
#include <cuda_runtime.h>
#include <cuda_fp16.h>
#include <math.h>
#include <stdint.h>

#define N_NODES 10000
#define E_EDGES 160000
#define DCH 512
#define C_HEAD 256
#define HEADS 2
#define TDIM 128
#define MDIM 256
#define FDIM 384   // TDIM + MDIM
#define NCAT 2816  // 4*512 (q,k,v,skip) + 2*384 (p heads)

// ---------------- scratch (device globals) ----------------
__device__ float  g_q[N_NODES * DCH];
__device__ float  g_k[N_NODES * DCH];
__device__ float  g_v[N_NODES * DCH];
__device__ float  g_p[N_NODES * HEADS * FDIM];
__device__ float  g_WeT[HEADS * C_HEAD * FDIM];       // WeT[h][c][f] = We[f][h*C+c]
__device__ float  g_pbias[HEADS * FDIM];
__device__ int    g_deg[N_NODES];
__device__ int    g_cur[N_NODES];
__device__ int    g_off[N_NODES + 1];
__device__ int    g_perm[E_EDGES];
// fp16 operands: A-side split (hi+lo), B-side single
__device__ __half g_xhi[N_NODES * DCH];
__device__ __half g_xlo[N_NODES * DCH];
__device__ __half g_w[NCAT * DCH];                     // K-major: [n][k], single fp16
__device__ __half g_wekt[HEADS * C_HEAD * FDIM];       // [h][n][k] single fp16
__device__ __half g_ghi[N_NODES * HEADS * FDIM];       // [n][h*384+f]
__device__ __half g_glo[N_NODES * HEADS * FDIM];

// ================= mma.sync helpers (fp16 in, fp32 accum) =================
__device__ __forceinline__ void mma_f16_acc(
    float c[4], uint32_t a0, uint32_t a1, uint32_t a2, uint32_t a3,
    uint32_t b0, uint32_t b1)
{
    asm volatile(
        "mma.sync.aligned.m16n8k16.row.col.f32.f16.f16.f32 "
        "{%0,%1,%2,%3}, {%4,%5,%6,%7}, {%8,%9}, {%0,%1,%2,%3};"
        : "+f"(c[0]), "+f"(c[1]), "+f"(c[2]), "+f"(c[3])
        : "r"(a0), "r"(a1), "r"(a2), "r"(a3), "r"(b0), "r"(b1));
}
__device__ __forceinline__ void ldm_x4(uint32_t& r0, uint32_t& r1,
                                       uint32_t& r2, uint32_t& r3, uint32_t a) {
    asm volatile("ldmatrix.sync.aligned.m8n8.x4.shared.b16 {%0,%1,%2,%3}, [%4];"
                 : "=r"(r0), "=r"(r1), "=r"(r2), "=r"(r3) : "r"(a));
}

#define LDK 24                       // 48B row stride: 16B-aligned, ldmatrix conflict-free
#define STG_ELEMS (128 * LDK)        // 3072 fp16 = 6144 B per array
#define AR_BYTES (STG_ELEMS * 2)
#define ST_BYTES (3 * AR_BYTES)      // Ah, Al, B = 18432 B per stage

// ---------------- mma mainloop: 128x128 CTA tile, BK=16, double-buffered -------
// 256 threads, 8 warps, warp tile 32x64 (4m x 2n grid). 2-product split-fp16.
__device__ __forceinline__ void mma_mainloop(
    const __half* __restrict__ Ahi, const __half* __restrict__ Alo,
    int lda, int m0, int Mrows,
    const __half* __restrict__ B, int ldb, int n0, int K,
    float cacc[2][8][4])
{
    __shared__ __align__(16) char smraw[2 * ST_BYTES];   // 36 KB static

    const int tid = threadIdx.x;
    const int row = tid >> 1;
    const int colh = (tid & 1) * 8;
    const int lane = tid & 31;
    const int wid = tid >> 5;
    const int wm = (wid & 3) * 32;
    const int wn = (wid >> 2) * 64;
    const int lr = lane & 7, seg = lane >> 3;

    const bool aOk = (m0 + row) < Mrows;
    const int arow = aOk ? (m0 + row) : 0;
    const __half* Aph = Ahi + (size_t)arow * lda + colh;
    const __half* Apl = Alo + (size_t)arow * lda + colh;
    const __half* Bp  = B + (size_t)(n0 + row) * ldb + colh;

    const uint32_t smBase = (uint32_t)__cvta_generic_to_shared(smraw);
    const uint32_t wrOff = (row * LDK + colh) * 2;

    const int nkt = K >> 4;

    uint32_t bOffP[4], aOffM[2];
#pragma unroll
    for (int p = 0; p < 4; p++)
        bOffP[p] = ((wn + (2 * p + (seg >> 1)) * 8 + lr) * LDK + (seg & 1) * 8) * 2;
#pragma unroll
    for (int mt = 0; mt < 2; mt++)
        aOffM[mt] = ((wm + mt * 16 + (seg & 1) * 8 + lr) * LDK + (seg >> 1) * 8) * 2;

    const uint4 z4 = make_uint4(0u, 0u, 0u, 0u);
    uint4 rah = aOk ? *(const uint4*)Aph : z4;
    uint4 ral = aOk ? *(const uint4*)Apl : z4;
    uint4 rb  = *(const uint4*)Bp;

    {
        char* b = smraw + wrOff;
        *(uint4*)(b + 0 * AR_BYTES) = rah;
        *(uint4*)(b + 1 * AR_BYTES) = ral;
        *(uint4*)(b + 2 * AR_BYTES) = rb;
    }
    __syncthreads();

    for (int kt = 0; kt < nkt; kt++) {
        const int s = kt & 1;
        if (kt + 1 < nkt) {
            const int ko = (kt + 1) * 16;
            rah = aOk ? *(const uint4*)(Aph + ko) : z4;
            ral = aOk ? *(const uint4*)(Apl + ko) : z4;
            rb  = *(const uint4*)(Bp + ko);
        }

        const uint32_t sb = smBase + s * ST_BYTES;
        uint32_t bh[8][2];
#pragma unroll
        for (int p = 0; p < 4; p++)
            ldm_x4(bh[2 * p][0], bh[2 * p][1], bh[2 * p + 1][0], bh[2 * p + 1][1],
                   sb + 2 * AR_BYTES + bOffP[p]);
#pragma unroll
        for (int mt = 0; mt < 2; mt++) {
            uint32_t ah0, ah1, ah2, ah3, al0, al1, al2, al3;
            ldm_x4(ah0, ah1, ah2, ah3, sb + 0 * AR_BYTES + aOffM[mt]);
            ldm_x4(al0, al1, al2, al3, sb + 1 * AR_BYTES + aOffM[mt]);
#pragma unroll
            for (int nt = 0; nt < 8; nt++) {
                mma_f16_acc(cacc[mt][nt], ah0, ah1, ah2, ah3, bh[nt][0], bh[nt][1]);
                mma_f16_acc(cacc[mt][nt], al0, al1, al2, al3, bh[nt][0], bh[nt][1]);
            }
        }

        if (kt + 1 < nkt) {
            char* b = smraw + (s ^ 1) * ST_BYTES + wrOff;
            *(uint4*)(b + 0 * AR_BYTES) = rah;
            *(uint4*)(b + 1 * AR_BYTES) = ral;
            *(uint4*)(b + 2 * AR_BYTES) = rb;
            __syncthreads();
        }
    }
}

// ---------------- kernel 1: fused projections q/k/v/skip/p ----------------
__global__ void __launch_bounds__(256, 2) mma_proj(
    const float* __restrict__ bq, const float* __restrict__ bk,
    const float* __restrict__ bv, const float* __restrict__ bs,
    float* __restrict__ out)
{
    float cacc[2][8][4] = {};
    const int j = blockIdx.x;
    const int m0 = blockIdx.y * 128;
    mma_mainloop(g_xhi, g_xlo, DCH, m0, N_NODES,
                 g_w, DCH, j * 128, DCH, cacc);

    const int lane = threadIdx.x & 31, wid = threadIdx.x >> 5;
    const int wm = (wid & 3) * 32, wn = (wid >> 2) * 64;
    const int g = lane >> 2, t = lane & 3;

    float* dst; const float* bvec; int col0, ldc;
    if (j < 16) {
        int seg = j >> 2;
        dst = (seg == 0) ? g_q : (seg == 1) ? g_k : (seg == 2) ? g_v : out;
        bvec = (seg == 0) ? bq : (seg == 1) ? bk : (seg == 2) ? bv : bs;
        col0 = (j & 3) * 128; ldc = DCH;
    } else {
        dst = g_p; bvec = g_pbias;
        col0 = (j - 16) * 128; ldc = HEADS * FDIM;
    }
#pragma unroll
    for (int mt = 0; mt < 2; mt++) {
#pragma unroll
        for (int nt = 0; nt < 8; nt++) {
            int gc = col0 + wn + nt * 8 + 2 * t;
            float b0v = bvec[gc], b1v = bvec[gc + 1];
            int r0 = m0 + wm + mt * 16 + g;
            if (r0 < N_NODES) {
                float2 v = make_float2(cacc[mt][nt][0] + b0v, cacc[mt][nt][1] + b1v);
                *(float2*)&dst[(size_t)r0 * ldc + gc] = v;
            }
            int r1 = r0 + 8;
            if (r1 < N_NODES) {
                float2 v = make_float2(cacc[mt][nt][2] + b0v, cacc[mt][nt][3] + b1v);
                *(float2*)&dst[(size_t)r1 * ldc + gc] = v;
            }
        }
    }
}

// ---------------- kernel 2: out += G @ We (per head) ----------------
__global__ void __launch_bounds__(256, 2) mma_out(float* __restrict__ out)
{
    float cacc[2][8][4] = {};
    const int j = blockIdx.x;
    const int h = j >> 1, jt = j & 1;
    const int m0 = blockIdx.y * 128;
    mma_mainloop(g_ghi + h * FDIM, g_glo + h * FDIM, HEADS * FDIM, m0, N_NODES,
                 g_wekt + (size_t)h * C_HEAD * FDIM, FDIM, jt * 128, FDIM, cacc);

    const int lane = threadIdx.x & 31, wid = threadIdx.x >> 5;
    const int wm = (wid & 3) * 32, wn = (wid >> 2) * 64;
    const int g = lane >> 2, t = lane & 3;
    const int col0 = h * C_HEAD + jt * 128;

#pragma unroll
    for (int mt = 0; mt < 2; mt++) {
#pragma unroll
        for (int nt = 0; nt < 8; nt++) {
            int gc = col0 + wn + nt * 8 + 2 * t;
            int r0 = m0 + wm + mt * 16 + g;
            if (r0 < N_NODES) {
                float2* op = (float2*)&out[(size_t)r0 * DCH + gc];
                float2 v = *op;
                v.x += cacc[mt][nt][0]; v.y += cacc[mt][nt][1];
                *op = v;
            }
            int r1 = r0 + 8;
            if (r1 < N_NODES) {
                float2* op = (float2*)&out[(size_t)r1 * DCH + gc];
                float2 v = *op;
                v.x += cacc[mt][nt][2]; v.y += cacc[mt][nt][3];
                *op = v;
            }
        }
    }
}

// ---------------- fp32 GEMM tile (M = Wq @ WeT, writes single fp16 weights) ------
__device__ __forceinline__ void gemm_tile_w(
    const float* __restrict__ A, int lda,
    const float* __restrict__ B, int ldb,
    int K, int bm, int bn,
    __half* wdst, int wrow0,
    float As[2][16][136], float Bs[2][16][128])
{
    const int tid = threadIdx.x;
    const int tx = tid & 15, ty = tid >> 4;
    const int aRow = tid >> 2;
    const int aCol = (tid & 3) * 4;
    const int bRow = tid >> 4;
    const int bCol = (tid & 15) * 4;

    const float* Ap0 = A + (size_t)(bm + aRow) * lda + aCol;
    const float* Ap1 = A + (size_t)(bm + aRow + 64) * lda + aCol;
    const float* Bp0 = B + (size_t)bRow * ldb + bn + bCol;
    const float* Bp1 = Bp0 + 64;
    const int nkt = K >> 4;

    float4 a0r = *(const float4*)Ap0;
    float4 a1r = *(const float4*)Ap1;
    float4 b0r = *(const float4*)Bp0;
    float4 b1r = *(const float4*)Bp1;

    As[0][aCol + 0][aRow] = a0r.x; As[0][aCol + 1][aRow] = a0r.y;
    As[0][aCol + 2][aRow] = a0r.z; As[0][aCol + 3][aRow] = a0r.w;
    As[0][aCol + 0][aRow + 64] = a1r.x; As[0][aCol + 1][aRow + 64] = a1r.y;
    As[0][aCol + 2][aRow + 64] = a1r.z; As[0][aCol + 3][aRow + 64] = a1r.w;
    *(float4*)&Bs[0][bRow][bCol] = b0r;
    *(float4*)&Bs[0][bRow][bCol + 64] = b1r;
    __syncthreads();

    float acc[8][8];
#pragma unroll
    for (int i = 0; i < 8; i++)
#pragma unroll
        for (int jj = 0; jj < 8; jj++) acc[i][jj] = 0.f;

    for (int kt = 0; kt < nkt; kt++) {
        const int s = kt & 1;
        if (kt + 1 < nkt) {
            const int ko = (kt + 1) * 16;
            a0r = *(const float4*)(Ap0 + ko);
            a1r = *(const float4*)(Ap1 + ko);
            b0r = *(const float4*)(Bp0 + (size_t)ko * ldb);
            b1r = *(const float4*)(Bp1 + (size_t)ko * ldb);
        }
#pragma unroll
        for (int kk = 0; kk < 16; kk++) {
            float4 av0 = *(const float4*)&As[s][kk][ty * 8];
            float4 av1 = *(const float4*)&As[s][kk][ty * 8 + 4];
            float4 bv0 = *(const float4*)&Bs[s][kk][tx * 4];
            float4 bv1 = *(const float4*)&Bs[s][kk][tx * 4 + 64];
            float ar[8] = {av0.x, av0.y, av0.z, av0.w, av1.x, av1.y, av1.z, av1.w};
            float br[8] = {bv0.x, bv0.y, bv0.z, bv0.w, bv1.x, bv1.y, bv1.z, bv1.w};
#pragma unroll
            for (int i = 0; i < 8; i++)
#pragma unroll
                for (int jj = 0; jj < 8; jj++) acc[i][jj] += ar[i] * br[jj];
        }
        if (kt + 1 < nkt) {
            __syncthreads();
            const int s1 = s ^ 1;
            As[s1][aCol + 0][aRow] = a0r.x; As[s1][aCol + 1][aRow] = a0r.y;
            As[s1][aCol + 2][aRow] = a0r.z; As[s1][aCol + 3][aRow] = a0r.w;
            As[s1][aCol + 0][aRow + 64] = a1r.x; As[s1][aCol + 1][aRow + 64] = a1r.y;
            As[s1][aCol + 2][aRow + 64] = a1r.z; As[s1][aCol + 3][aRow + 64] = a1r.w;
            *(float4*)&Bs[s1][bRow][bCol] = b0r;
            *(float4*)&Bs[s1][bRow][bCol + 64] = b1r;
            __syncthreads();
        }
    }

#pragma unroll
    for (int i = 0; i < 8; i++) {
        int kk = bm + ty * 8 + i;
#pragma unroll
        for (int jj = 0; jj < 8; jj++) {
            int f = bn + ((jj < 4) ? (tx * 4 + jj) : (64 + tx * 4 + jj - 4));
            int n = wrow0 + f;
            wdst[(size_t)n * DCH + kk] = __float2half_rn(acc[i][jj]);
        }
    }
}

__global__ void __launch_bounds__(256) gemm_m_kernel(const float* __restrict__ Wq) {
    __shared__ __align__(16) float As[2][16][136];
    __shared__ __align__(16) float Bs[2][16][128];
    int h = blockIdx.z;
    gemm_tile_w(Wq + h * C_HEAD, DCH,
                g_WeT + (size_t)h * C_HEAD * FDIM, FDIM,
                C_HEAD, blockIdx.y * 128, blockIdx.x * 128,
                g_w, 4 * DCH + h * FDIM, As, Bs);
}

// ---------------- prep: conv x (split), conv W (single), conv WeKT, pbias --------
#define PB_X  20000
#define PB_W  4096
#define PB_WE 768
#define PB_PB 3
__global__ void misc_prep(const float* __restrict__ x, const float* __restrict__ We,
                          const float* __restrict__ bq,
                          const float* __restrict__ Wq, const float* __restrict__ Wk,
                          const float* __restrict__ Wv, const float* __restrict__ Ws)
{
    int b = blockIdx.x, t = threadIdx.x;
    if (b < PB_X) {
        int i = b * 256 + t;
        float v = x[i];
        __half h = __float2half_rn(v);
        g_xhi[i] = h;
        g_xlo[i] = __float2half_rn(v - __half2float(h));
    } else if (b < PB_X + PB_W) {
        int idx = (b - PB_X) * 256 + t;
        int k = idx >> 11, n = idx & 2047;
        int seg = n >> 9, cc = n & 511;
        const float* W = (seg == 0) ? Wq : (seg == 1) ? Wk : (seg == 2) ? Wv : Ws;
        g_w[(size_t)n * DCH + k] = __float2half_rn(W[(size_t)k * DCH + cc]);
    } else if (b < PB_X + PB_W + PB_WE) {
        int idx = (b - PB_X - PB_W) * 256 + t;   // [h][n][k] with k fastest
        int h = idx / (C_HEAD * FDIM);
        int r = idx - h * (C_HEAD * FDIM);
        int n = r / FDIM, k = r - n * FDIM;
        g_wekt[idx] = __float2half_rn(We[(size_t)k * DCH + h * C_HEAD + n]);
    } else {
        int i = (b - PB_X - PB_W - PB_WE) * 256 + t;
        if (i < HEADS * FDIM) {
            int h = i / FDIM, f = i - h * FDIM;
            float s = 0.f;
            for (int c = 0; c < C_HEAD; c++)
                s += bq[h * C_HEAD + c] * We[(size_t)f * DCH + h * C_HEAD + c];
            g_pbias[i] = s;
        }
    }
}

// ---------------- We transpose ----------------
__global__ void transpose_we_kernel(const float* __restrict__ We) {
    int i = blockIdx.x * 256 + threadIdx.x;
    if (i < HEADS * C_HEAD * FDIM) {
        int h = i / (C_HEAD * FDIM);
        int r = i % (C_HEAD * FDIM);
        int c = r / FDIM;
        int f = r % FDIM;
        g_WeT[i] = We[(size_t)f * DCH + h * C_HEAD + c];
    }
}

// ---------------- CSR build ----------------
__global__ void zero_deg_kernel() {
    int i = blockIdx.x * 256 + threadIdx.x;
    if (i < N_NODES) g_deg[i] = 0;
}
__global__ void count_deg_kernel(const int* __restrict__ ei) {
    int i = blockIdx.x * 256 + threadIdx.x;
    if (i < E_EDGES) atomicAdd(&g_deg[ei[E_EDGES + i]], 1);
}
__global__ void __launch_bounds__(1024) scan_kernel() {
    __shared__ int part[1024];
    int tid = threadIdx.x;
    int base = tid * 10;
    int local[10];
    int s = 0;
#pragma unroll
    for (int j = 0; j < 10; j++) {
        int idx = base + j;
        int d = (idx < N_NODES) ? g_deg[idx] : 0;
        local[j] = d;
        s += d;
    }
    part[tid] = s;
    __syncthreads();
    for (int off = 1; off < 1024; off <<= 1) {
        int v = part[tid];
        int add = (tid >= off) ? part[tid - off] : 0;
        __syncthreads();
        part[tid] = v + add;
        __syncthreads();
    }
    int run = (tid > 0) ? part[tid - 1] : 0;
#pragma unroll
    for (int j = 0; j < 10; j++) {
        int idx = base + j;
        if (idx < N_NODES) {
            g_off[idx] = run;
            run += local[j];
            g_cur[idx] = 0;
        }
    }
    if (tid == 1023) g_off[N_NODES] = part[1023];
}
__global__ void scatter_perm_kernel(const int* __restrict__ ei) {
    int i = blockIdx.x * 256 + threadIdx.x;
    if (i < E_EDGES) {
        int d = ei[E_EDGES + i];
        int p = g_off[d] + atomicAdd(&g_cur[d], 1);
        g_perm[p] = i;
    }
}

// ---------------- fused edge logits + online softmax + aggregation ----------------
// R12 structure: separate stage / logit / softmax / accumulate phases.
#define CHUNK 12
__global__ void __launch_bounds__(128) fused_attn_kernel(
    const int* __restrict__ ei, const float* __restrict__ tfeat,
    const float* __restrict__ msg, float* __restrict__ out)
{
    const int n = blockIdx.x;
    const int tid = threadIdx.x;
    const int beg = g_off[n];
    const int deg = g_off[n + 1] - beg;

    if (deg == 0) {
        __half z = __float2half_rn(0.f);
#pragma unroll
        for (int l = 0; l < 3; l++) {
            size_t gi = (size_t)n * (HEADS * FDIM) + tid * 3 + l;
            g_ghi[gi] = z;        g_glo[gi] = z;
            g_ghi[gi + FDIM] = z; g_glo[gi + FDIM] = z;
        }
        return;
    }

    __shared__ __align__(16) float sq[DCH];
    __shared__ __align__(16) float sp[HEADS * FDIM];
    __shared__ __align__(16) float sea[CHUNK][FDIM];
    __shared__ float slog0[CHUNK], slog1[CHUNK];
    __shared__ float sw0[CHUNK], sw1[CHUNK];
    __shared__ int   ssrc[CHUNK];

    ((float4*)sq)[tid] = ((const float4*)(g_q + (size_t)n * DCH))[tid];
#pragma unroll
    for (int i = tid; i < (HEADS * FDIM) / 4; i += 128)
        ((float4*)sp)[i] = ((const float4*)(g_p + (size_t)n * (HEADS * FDIM)))[i];

    const int wid = tid >> 5, lane = tid & 31;

    float acc0 = 0.f, acc1 = 0.f, acc2 = 0.f, acc3 = 0.f;
    float ga0[3] = {0.f, 0.f, 0.f}, ga1[3] = {0.f, 0.f, 0.f};
    float rm0 = -1e30f, rm1 = -1e30f, den0 = 0.f, den1 = 0.f;

    for (int base = 0; base < deg; base += CHUNK) {
        const int cnt = min(CHUNK, deg - base);
        __syncthreads();

        // phase a: stage edge_attr chunk (warp per edge, strided)
        for (int j = wid; j < cnt; j += 4) {
            int e = g_perm[beg + base + j];
            if (lane == 0) ssrc[j] = ei[e];
            const float4* tr = (const float4*)(tfeat + (size_t)e * TDIM);
            const float4* mr = (const float4*)(msg + (size_t)e * MDIM);
            ((float4*)sea[j])[lane]      = tr[lane];
            ((float4*)sea[j])[32 + lane] = mr[lane];
            ((float4*)sea[j])[64 + lane] = mr[32 + lane];
        }
        __syncthreads();

        // phase b: logits (warp per edge)
        for (int j = wid; j < cnt; j += 4) {
            const float4* kr = (const float4*)(g_k + (size_t)ssrc[j] * DCH);
            float a0 = 0.f, a1 = 0.f;
#pragma unroll
            for (int it = 0; it < 2; it++) {
                float4 kv = kr[lane + 32 * it];
                float4 qv = ((const float4*)sq)[lane + 32 * it];
                a0 += kv.x * qv.x + kv.y * qv.y + kv.z * qv.z + kv.w * qv.w;
            }
#pragma unroll
            for (int it = 2; it < 4; it++) {
                float4 kv = kr[lane + 32 * it];
                float4 qv = ((const float4*)sq)[lane + 32 * it];
                a1 += kv.x * qv.x + kv.y * qv.y + kv.z * qv.z + kv.w * qv.w;
            }
#pragma unroll
            for (int it = 0; it < 3; it++) {
                float4 ev = ((const float4*)sea[j])[lane + 32 * it];
                float4 p0 = ((const float4*)sp)[lane + 32 * it];
                float4 p1 = ((const float4*)sp)[96 + lane + 32 * it];
                a0 += ev.x * p0.x + ev.y * p0.y + ev.z * p0.z + ev.w * p0.w;
                a1 += ev.x * p1.x + ev.y * p1.y + ev.z * p1.z + ev.w * p1.w;
            }
#pragma unroll
            for (int o = 16; o; o >>= 1) {
                a0 += __shfl_xor_sync(0xffffffffu, a0, o);
                a1 += __shfl_xor_sync(0xffffffffu, a1, o);
            }
            if (lane == 0) {
                slog0[j] = a0 * 0.0625f;
                slog1[j] = a1 * 0.0625f;
            }
        }
        __syncthreads();

        // phase c: online-softmax rescale + chunk weights
        float cm0 = -1e30f, cm1 = -1e30f;
        for (int j = 0; j < cnt; j++) {
            cm0 = fmaxf(cm0, slog0[j]);
            cm1 = fmaxf(cm1, slog1[j]);
        }
        float nm0 = fmaxf(rm0, cm0), nm1 = fmaxf(rm1, cm1);
        float sc0 = expf(rm0 - nm0), sc1 = expf(rm1 - nm1);
        float scv = (tid < 64) ? sc0 : sc1;
        acc0 *= scv; acc1 *= scv; acc2 *= scv; acc3 *= scv;
#pragma unroll
        for (int l = 0; l < 3; l++) { ga0[l] *= sc0; ga1[l] *= sc1; }
        den0 *= sc0; den1 *= sc1;
        rm0 = nm0; rm1 = nm1;
        if (tid < cnt) {
            sw0[tid] = expf(slog0[tid] - nm0);
            sw1[tid] = expf(slog1[tid] - nm1);
        }
        __syncthreads();

        // phase d: accumulate v and G from staged chunk
        for (int j = 0; j < cnt; j++) {
            float w0 = sw0[j], w1 = sw1[j];
            float wv = (tid < 64) ? w0 : w1;
            float4 vv = *(const float4*)(g_v + (size_t)ssrc[j] * DCH + tid * 4);
            acc0 += wv * vv.x; acc1 += wv * vv.y;
            acc2 += wv * vv.z; acc3 += wv * vv.w;
            const float* er = sea[j] + tid * 3;
            float e0 = er[0], e1 = er[1], e2 = er[2];
            ga0[0] += w0 * e0; ga0[1] += w0 * e1; ga0[2] += w0 * e2;
            ga1[0] += w1 * e0; ga1[1] += w1 * e1; ga1[2] += w1 * e2;
            den0 += w0; den1 += w1;
        }
    }

    float inv0 = 1.f / (den0 + 1e-16f);
    float inv1 = 1.f / (den1 + 1e-16f);
    float invv = (tid < 64) ? inv0 : inv1;

    float4* op = (float4*)(out + (size_t)n * DCH + tid * 4);
    float4 o = *op;
    o.x += acc0 * invv; o.y += acc1 * invv;
    o.z += acc2 * invv; o.w += acc3 * invv;
    *op = o;

#pragma unroll
    for (int l = 0; l < 3; l++) {
        size_t gi = (size_t)n * (HEADS * FDIM) + tid * 3 + l;
        float v0 = ga0[l] * inv0;
        float v1 = ga1[l] * inv1;
        __half h0 = __float2half_rn(v0);
        __half h1 = __float2half_rn(v1);
        g_ghi[gi] = h0;
        g_glo[gi] = __float2half_rn(v0 - __half2float(h0));
        g_ghi[gi + FDIM] = h1;
        g_glo[gi + FDIM] = __float2half_rn(v1 - __half2float(h1));
    }
}

// ---------------- launch ----------------
extern "C" void kernel_launch(void* const* d_in, const int* in_sizes, int n_in,
                              void* d_out, int out_size)
{
    const float* x     = (const float*)d_in[0];
    const int*   ei    = (const int*)d_in[2];
    const float* tfeat = (const float*)d_in[3];
    const float* msg   = (const float*)d_in[4];
    const float* Wq    = (const float*)d_in[5];
    const float* bq    = (const float*)d_in[6];
    const float* Wk    = (const float*)d_in[7];
    const float* bk    = (const float*)d_in[8];
    const float* Wv    = (const float*)d_in[9];
    const float* bv    = (const float*)d_in[10];
    const float* We    = (const float*)d_in[11];
    const float* Ws    = (const float*)d_in[12];
    const float* bs    = (const float*)d_in[13];
    float* out = (float*)d_out;

    // 1: conversions + pbias
    misc_prep<<<PB_X + PB_W + PB_WE + PB_PB, 256>>>(x, We, bq, Wq, Wk, Wv, Ws);
    // 2: WeT (fp32, for M)
    transpose_we_kernel<<<(HEADS * C_HEAD * FDIM + 255) / 256, 256>>>(We);
    // 3: M_h = Wq_h @ WeT_h  (written as single fp16 into g_w rows 2048+)
    dim3 gm(FDIM / 128, 4, HEADS);
    gemm_m_kernel<<<gm, 256>>>(Wq);
    // 4: tensor-core projection GEMM  <-- profiled slot
    dim3 gproj(NCAT / 128, (N_NODES + 127) / 128);
    mma_proj<<<gproj, 256>>>(bq, bk, bv, bs, out);
    // 5-8: CSR
    zero_deg_kernel<<<(N_NODES + 255) / 256, 256>>>();
    count_deg_kernel<<<(E_EDGES + 255) / 256, 256>>>(ei);
    scan_kernel<<<1, 1024>>>();
    scatter_perm_kernel<<<(E_EDGES + 255) / 256, 256>>>(ei);
    // 9: fused edge logits + online softmax + aggregation
    fused_attn_kernel<<<N_NODES, 128>>>(ei, tfeat, msg, out);
    // 10: out += G @ We  (mma.sync, 2-product split-fp16)
    dim3 gout(2 * HEADS, (N_NODES + 127) / 128);
    mma_out<<<gout, 256>>>(out);
}

// round 15
// speedup vs baseline: 1.1159x; 1.0371x over previous
#include <cuda_runtime.h>
#include <cuda_fp16.h>
#include <math.h>
#include <stdint.h>

#define N_NODES 10000
#define E_EDGES 160000
#define DCH 512
#define C_HEAD 256
#define HEADS 2
#define TDIM 128
#define MDIM 256
#define FDIM 384   // TDIM + MDIM
#define NCAT 2816  // 4*512 (q,k,v,skip) + 2*384 (p heads)

// ---------------- scratch (device globals) ----------------
__device__ float  g_q[N_NODES * DCH];
__device__ __half g_kh[N_NODES * DCH];                // fp16 k (written by mma_proj)
__device__ __half g_vh[N_NODES * DCH];                // fp16 v (written by mma_proj)
__device__ float  g_p[N_NODES * HEADS * FDIM];
__device__ float  g_WeT[HEADS * C_HEAD * FDIM];       // WeT[h][c][f] = We[f][h*C+c]
__device__ float  g_pbias[HEADS * FDIM];
__device__ int    g_deg[N_NODES];
__device__ int    g_cur[N_NODES];
__device__ int    g_off[N_NODES + 1];
__device__ int    g_perm[E_EDGES];
// fp16 operands: A-side split (hi+lo), B-side single
__device__ __half g_xhi[N_NODES * DCH];
__device__ __half g_xlo[N_NODES * DCH];
__device__ __half g_w[NCAT * DCH];                     // K-major: [n][k], single fp16
__device__ __half g_wekt[HEADS * C_HEAD * FDIM];       // [h][n][k] single fp16
__device__ __half g_ghi[N_NODES * HEADS * FDIM];       // [n][h*384+f]
__device__ __half g_glo[N_NODES * HEADS * FDIM];

// ================= mma.sync helpers (fp16 in, fp32 accum) =================
__device__ __forceinline__ void mma_f16_acc(
    float c[4], uint32_t a0, uint32_t a1, uint32_t a2, uint32_t a3,
    uint32_t b0, uint32_t b1)
{
    asm volatile(
        "mma.sync.aligned.m16n8k16.row.col.f32.f16.f16.f32 "
        "{%0,%1,%2,%3}, {%4,%5,%6,%7}, {%8,%9}, {%0,%1,%2,%3};"
        : "+f"(c[0]), "+f"(c[1]), "+f"(c[2]), "+f"(c[3])
        : "r"(a0), "r"(a1), "r"(a2), "r"(a3), "r"(b0), "r"(b1));
}
__device__ __forceinline__ void ldm_x4(uint32_t& r0, uint32_t& r1,
                                       uint32_t& r2, uint32_t& r3, uint32_t a) {
    asm volatile("ldmatrix.sync.aligned.m8n8.x4.shared.b16 {%0,%1,%2,%3}, [%4];"
                 : "=r"(r0), "=r"(r1), "=r"(r2), "=r"(r3) : "r"(a));
}

#define LDK 24                       // 48B row stride: 16B-aligned, ldmatrix conflict-free
#define STG_ELEMS (128 * LDK)        // 3072 fp16 = 6144 B per array
#define AR_BYTES (STG_ELEMS * 2)
#define ST_BYTES (3 * AR_BYTES)      // Ah, Al, B = 18432 B per stage

// ---------------- mma mainloop: 128x128 CTA tile, BK=16, double-buffered -------
// 256 threads, 8 warps, warp tile 32x64 (4m x 2n grid). 2-product split-fp16.
__device__ __forceinline__ void mma_mainloop(
    const __half* __restrict__ Ahi, const __half* __restrict__ Alo,
    int lda, int m0, int Mrows,
    const __half* __restrict__ B, int ldb, int n0, int K,
    float cacc[2][8][4])
{
    __shared__ __align__(16) char smraw[2 * ST_BYTES];   // 36 KB static

    const int tid = threadIdx.x;
    const int row = tid >> 1;
    const int colh = (tid & 1) * 8;
    const int lane = tid & 31;
    const int wid = tid >> 5;
    const int wm = (wid & 3) * 32;
    const int wn = (wid >> 2) * 64;
    const int lr = lane & 7, seg = lane >> 3;

    const bool aOk = (m0 + row) < Mrows;
    const int arow = aOk ? (m0 + row) : 0;
    const __half* Aph = Ahi + (size_t)arow * lda + colh;
    const __half* Apl = Alo + (size_t)arow * lda + colh;
    const __half* Bp  = B + (size_t)(n0 + row) * ldb + colh;

    const uint32_t smBase = (uint32_t)__cvta_generic_to_shared(smraw);
    const uint32_t wrOff = (row * LDK + colh) * 2;

    const int nkt = K >> 4;

    uint32_t bOffP[4], aOffM[2];
#pragma unroll
    for (int p = 0; p < 4; p++)
        bOffP[p] = ((wn + (2 * p + (seg >> 1)) * 8 + lr) * LDK + (seg & 1) * 8) * 2;
#pragma unroll
    for (int mt = 0; mt < 2; mt++)
        aOffM[mt] = ((wm + mt * 16 + (seg & 1) * 8 + lr) * LDK + (seg >> 1) * 8) * 2;

    const uint4 z4 = make_uint4(0u, 0u, 0u, 0u);
    uint4 rah = aOk ? *(const uint4*)Aph : z4;
    uint4 ral = aOk ? *(const uint4*)Apl : z4;
    uint4 rb  = *(const uint4*)Bp;

    {
        char* b = smraw + wrOff;
        *(uint4*)(b + 0 * AR_BYTES) = rah;
        *(uint4*)(b + 1 * AR_BYTES) = ral;
        *(uint4*)(b + 2 * AR_BYTES) = rb;
    }
    __syncthreads();

    for (int kt = 0; kt < nkt; kt++) {
        const int s = kt & 1;
        if (kt + 1 < nkt) {
            const int ko = (kt + 1) * 16;
            rah = aOk ? *(const uint4*)(Aph + ko) : z4;
            ral = aOk ? *(const uint4*)(Apl + ko) : z4;
            rb  = *(const uint4*)(Bp + ko);
        }

        const uint32_t sb = smBase + s * ST_BYTES;
        uint32_t bh[8][2];
#pragma unroll
        for (int p = 0; p < 4; p++)
            ldm_x4(bh[2 * p][0], bh[2 * p][1], bh[2 * p + 1][0], bh[2 * p + 1][1],
                   sb + 2 * AR_BYTES + bOffP[p]);
#pragma unroll
        for (int mt = 0; mt < 2; mt++) {
            uint32_t ah0, ah1, ah2, ah3, al0, al1, al2, al3;
            ldm_x4(ah0, ah1, ah2, ah3, sb + 0 * AR_BYTES + aOffM[mt]);
            ldm_x4(al0, al1, al2, al3, sb + 1 * AR_BYTES + aOffM[mt]);
#pragma unroll
            for (int nt = 0; nt < 8; nt++) {
                mma_f16_acc(cacc[mt][nt], ah0, ah1, ah2, ah3, bh[nt][0], bh[nt][1]);
                mma_f16_acc(cacc[mt][nt], al0, al1, al2, al3, bh[nt][0], bh[nt][1]);
            }
        }

        if (kt + 1 < nkt) {
            char* b = smraw + (s ^ 1) * ST_BYTES + wrOff;
            *(uint4*)(b + 0 * AR_BYTES) = rah;
            *(uint4*)(b + 1 * AR_BYTES) = ral;
            *(uint4*)(b + 2 * AR_BYTES) = rb;
            __syncthreads();
        }
    }
}

// ---------------- kernel 1: fused projections q/k/v/skip/p ----------------
// q, skip, p written fp32; k, v written fp16.
__global__ void __launch_bounds__(256, 2) mma_proj(
    const float* __restrict__ bq, const float* __restrict__ bk,
    const float* __restrict__ bv, const float* __restrict__ bs,
    float* __restrict__ out)
{
    float cacc[2][8][4] = {};
    const int j = blockIdx.x;
    const int m0 = blockIdx.y * 128;
    mma_mainloop(g_xhi, g_xlo, DCH, m0, N_NODES,
                 g_w, DCH, j * 128, DCH, cacc);

    const int lane = threadIdx.x & 31, wid = threadIdx.x >> 5;
    const int wm = (wid & 3) * 32, wn = (wid >> 2) * 64;
    const int g = lane >> 2, t = lane & 3;

    float* dstf = nullptr; __half* dsth = nullptr;
    const float* bvec; int col0, ldc;
    if (j < 16) {
        int seg = j >> 2;
        if (seg == 0)      { dstf = g_q;  bvec = bq; }
        else if (seg == 1) { dsth = g_kh; bvec = bk; }
        else if (seg == 2) { dsth = g_vh; bvec = bv; }
        else               { dstf = out;  bvec = bs; }
        col0 = (j & 3) * 128; ldc = DCH;
    } else {
        dstf = g_p; bvec = g_pbias;
        col0 = (j - 16) * 128; ldc = HEADS * FDIM;
    }
#pragma unroll
    for (int mt = 0; mt < 2; mt++) {
#pragma unroll
        for (int nt = 0; nt < 8; nt++) {
            int gc = col0 + wn + nt * 8 + 2 * t;
            float b0v = bvec[gc], b1v = bvec[gc + 1];
            int r0 = m0 + wm + mt * 16 + g;
            if (r0 < N_NODES) {
                float vx = cacc[mt][nt][0] + b0v, vy = cacc[mt][nt][1] + b1v;
                if (dstf) *(float2*)&dstf[(size_t)r0 * ldc + gc] = make_float2(vx, vy);
                else      *(__half2*)&dsth[(size_t)r0 * ldc + gc] = __floats2half2_rn(vx, vy);
            }
            int r1 = r0 + 8;
            if (r1 < N_NODES) {
                float vx = cacc[mt][nt][2] + b0v, vy = cacc[mt][nt][3] + b1v;
                if (dstf) *(float2*)&dstf[(size_t)r1 * ldc + gc] = make_float2(vx, vy);
                else      *(__half2*)&dsth[(size_t)r1 * ldc + gc] = __floats2half2_rn(vx, vy);
            }
        }
    }
}

// ---------------- kernel 2: out += G @ We (per head) ----------------
__global__ void __launch_bounds__(256, 2) mma_out(float* __restrict__ out)
{
    float cacc[2][8][4] = {};
    const int j = blockIdx.x;
    const int h = j >> 1, jt = j & 1;
    const int m0 = blockIdx.y * 128;
    mma_mainloop(g_ghi + h * FDIM, g_glo + h * FDIM, HEADS * FDIM, m0, N_NODES,
                 g_wekt + (size_t)h * C_HEAD * FDIM, FDIM, jt * 128, FDIM, cacc);

    const int lane = threadIdx.x & 31, wid = threadIdx.x >> 5;
    const int wm = (wid & 3) * 32, wn = (wid >> 2) * 64;
    const int g = lane >> 2, t = lane & 3;
    const int col0 = h * C_HEAD + jt * 128;

#pragma unroll
    for (int mt = 0; mt < 2; mt++) {
#pragma unroll
        for (int nt = 0; nt < 8; nt++) {
            int gc = col0 + wn + nt * 8 + 2 * t;
            int r0 = m0 + wm + mt * 16 + g;
            if (r0 < N_NODES) {
                float2* op = (float2*)&out[(size_t)r0 * DCH + gc];
                float2 v = *op;
                v.x += cacc[mt][nt][0]; v.y += cacc[mt][nt][1];
                *op = v;
            }
            int r1 = r0 + 8;
            if (r1 < N_NODES) {
                float2* op = (float2*)&out[(size_t)r1 * DCH + gc];
                float2 v = *op;
                v.x += cacc[mt][nt][2]; v.y += cacc[mt][nt][3];
                *op = v;
            }
        }
    }
}

// ---------------- fp32 GEMM tile (M = Wq @ WeT, writes single fp16 weights) ------
__device__ __forceinline__ void gemm_tile_w(
    const float* __restrict__ A, int lda,
    const float* __restrict__ B, int ldb,
    int K, int bm, int bn,
    __half* wdst, int wrow0,
    float As[2][16][136], float Bs[2][16][128])
{
    const int tid = threadIdx.x;
    const int tx = tid & 15, ty = tid >> 4;
    const int aRow = tid >> 2;
    const int aCol = (tid & 3) * 4;
    const int bRow = tid >> 4;
    const int bCol = (tid & 15) * 4;

    const float* Ap0 = A + (size_t)(bm + aRow) * lda + aCol;
    const float* Ap1 = A + (size_t)(bm + aRow + 64) * lda + aCol;
    const float* Bp0 = B + (size_t)bRow * ldb + bn + bCol;
    const float* Bp1 = Bp0 + 64;
    const int nkt = K >> 4;

    float4 a0r = *(const float4*)Ap0;
    float4 a1r = *(const float4*)Ap1;
    float4 b0r = *(const float4*)Bp0;
    float4 b1r = *(const float4*)Bp1;

    As[0][aCol + 0][aRow] = a0r.x; As[0][aCol + 1][aRow] = a0r.y;
    As[0][aCol + 2][aRow] = a0r.z; As[0][aCol + 3][aRow] = a0r.w;
    As[0][aCol + 0][aRow + 64] = a1r.x; As[0][aCol + 1][aRow + 64] = a1r.y;
    As[0][aCol + 2][aRow + 64] = a1r.z; As[0][aCol + 3][aRow + 64] = a1r.w;
    *(float4*)&Bs[0][bRow][bCol] = b0r;
    *(float4*)&Bs[0][bRow][bCol + 64] = b1r;
    __syncthreads();

    float acc[8][8];
#pragma unroll
    for (int i = 0; i < 8; i++)
#pragma unroll
        for (int jj = 0; jj < 8; jj++) acc[i][jj] = 0.f;

    for (int kt = 0; kt < nkt; kt++) {
        const int s = kt & 1;
        if (kt + 1 < nkt) {
            const int ko = (kt + 1) * 16;
            a0r = *(const float4*)(Ap0 + ko);
            a1r = *(const float4*)(Ap1 + ko);
            b0r = *(const float4*)(Bp0 + (size_t)ko * ldb);
            b1r = *(const float4*)(Bp1 + (size_t)ko * ldb);
        }
#pragma unroll
        for (int kk = 0; kk < 16; kk++) {
            float4 av0 = *(const float4*)&As[s][kk][ty * 8];
            float4 av1 = *(const float4*)&As[s][kk][ty * 8 + 4];
            float4 bv0 = *(const float4*)&Bs[s][kk][tx * 4];
            float4 bv1 = *(const float4*)&Bs[s][kk][tx * 4 + 64];
            float ar[8] = {av0.x, av0.y, av0.z, av0.w, av1.x, av1.y, av1.z, av1.w};
            float br[8] = {bv0.x, bv0.y, bv0.z, bv0.w, bv1.x, bv1.y, bv1.z, bv1.w};
#pragma unroll
            for (int i = 0; i < 8; i++)
#pragma unroll
                for (int jj = 0; jj < 8; jj++) acc[i][jj] += ar[i] * br[jj];
        }
        if (kt + 1 < nkt) {
            __syncthreads();
            const int s1 = s ^ 1;
            As[s1][aCol + 0][aRow] = a0r.x; As[s1][aCol + 1][aRow] = a0r.y;
            As[s1][aCol + 2][aRow] = a0r.z; As[s1][aCol + 3][aRow] = a0r.w;
            As[s1][aCol + 0][aRow + 64] = a1r.x; As[s1][aCol + 1][aRow + 64] = a1r.y;
            As[s1][aCol + 2][aRow + 64] = a1r.z; As[s1][aCol + 3][aRow + 64] = a1r.w;
            *(float4*)&Bs[s1][bRow][bCol] = b0r;
            *(float4*)&Bs[s1][bRow][bCol + 64] = b1r;
            __syncthreads();
        }
    }

#pragma unroll
    for (int i = 0; i < 8; i++) {
        int kk = bm + ty * 8 + i;
#pragma unroll
        for (int jj = 0; jj < 8; jj++) {
            int f = bn + ((jj < 4) ? (tx * 4 + jj) : (64 + tx * 4 + jj - 4));
            int n = wrow0 + f;
            wdst[(size_t)n * DCH + kk] = __float2half_rn(acc[i][jj]);
        }
    }
}

__global__ void __launch_bounds__(256) gemm_m_kernel(const float* __restrict__ Wq) {
    __shared__ __align__(16) float As[2][16][136];
    __shared__ __align__(16) float Bs[2][16][128];
    int h = blockIdx.z;
    gemm_tile_w(Wq + h * C_HEAD, DCH,
                g_WeT + (size_t)h * C_HEAD * FDIM, FDIM,
                C_HEAD, blockIdx.y * 128, blockIdx.x * 128,
                g_w, 4 * DCH + h * FDIM, As, Bs);
}

// ---------------- prep: conv x (split), conv W (single), conv WeKT, pbias --------
#define PB_X  20000
#define PB_W  4096
#define PB_WE 768
#define PB_PB 3
__global__ void misc_prep(const float* __restrict__ x, const float* __restrict__ We,
                          const float* __restrict__ bq,
                          const float* __restrict__ Wq, const float* __restrict__ Wk,
                          const float* __restrict__ Wv, const float* __restrict__ Ws)
{
    int b = blockIdx.x, t = threadIdx.x;
    if (b < PB_X) {
        int i = b * 256 + t;
        float v = x[i];
        __half h = __float2half_rn(v);
        g_xhi[i] = h;
        g_xlo[i] = __float2half_rn(v - __half2float(h));
    } else if (b < PB_X + PB_W) {
        int idx = (b - PB_X) * 256 + t;
        int k = idx >> 11, n = idx & 2047;
        int seg = n >> 9, cc = n & 511;
        const float* W = (seg == 0) ? Wq : (seg == 1) ? Wk : (seg == 2) ? Wv : Ws;
        g_w[(size_t)n * DCH + k] = __float2half_rn(W[(size_t)k * DCH + cc]);
    } else if (b < PB_X + PB_W + PB_WE) {
        int idx = (b - PB_X - PB_W) * 256 + t;   // [h][n][k] with k fastest
        int h = idx / (C_HEAD * FDIM);
        int r = idx - h * (C_HEAD * FDIM);
        int n = r / FDIM, k = r - n * FDIM;
        g_wekt[idx] = __float2half_rn(We[(size_t)k * DCH + h * C_HEAD + n]);
    } else {
        int i = (b - PB_X - PB_W - PB_WE) * 256 + t;
        if (i < HEADS * FDIM) {
            int h = i / FDIM, f = i - h * FDIM;
            float s = 0.f;
            for (int c = 0; c < C_HEAD; c++)
                s += bq[h * C_HEAD + c] * We[(size_t)f * DCH + h * C_HEAD + c];
            g_pbias[i] = s;
        }
    }
}

// ---------------- We transpose ----------------
__global__ void transpose_we_kernel(const float* __restrict__ We) {
    int i = blockIdx.x * 256 + threadIdx.x;
    if (i < HEADS * C_HEAD * FDIM) {
        int h = i / (C_HEAD * FDIM);
        int r = i % (C_HEAD * FDIM);
        int c = r / FDIM;
        int f = r % FDIM;
        g_WeT[i] = We[(size_t)f * DCH + h * C_HEAD + c];
    }
}

// ---------------- CSR build ----------------
__global__ void zero_deg_kernel() {
    int i = blockIdx.x * 256 + threadIdx.x;
    if (i < N_NODES) g_deg[i] = 0;
}
__global__ void count_deg_kernel(const int* __restrict__ ei) {
    int i = blockIdx.x * 256 + threadIdx.x;
    if (i < E_EDGES) atomicAdd(&g_deg[ei[E_EDGES + i]], 1);
}
__global__ void __launch_bounds__(1024) scan_kernel() {
    __shared__ int part[1024];
    int tid = threadIdx.x;
    int base = tid * 10;
    int local[10];
    int s = 0;
#pragma unroll
    for (int j = 0; j < 10; j++) {
        int idx = base + j;
        int d = (idx < N_NODES) ? g_deg[idx] : 0;
        local[j] = d;
        s += d;
    }
    part[tid] = s;
    __syncthreads();
    for (int off = 1; off < 1024; off <<= 1) {
        int v = part[tid];
        int add = (tid >= off) ? part[tid - off] : 0;
        __syncthreads();
        part[tid] = v + add;
        __syncthreads();
    }
    int run = (tid > 0) ? part[tid - 1] : 0;
#pragma unroll
    for (int j = 0; j < 10; j++) {
        int idx = base + j;
        if (idx < N_NODES) {
            g_off[idx] = run;
            run += local[j];
            g_cur[idx] = 0;
        }
    }
    if (tid == 1023) g_off[N_NODES] = part[1023];
}
__global__ void scatter_perm_kernel(const int* __restrict__ ei) {
    int i = blockIdx.x * 256 + threadIdx.x;
    if (i < E_EDGES) {
        int d = ei[E_EDGES + i];
        int p = g_off[d] + atomicAdd(&g_cur[d], 1);
        g_perm[p] = i;
    }
}

// ---------------- fused edge logits + online softmax + aggregation ----------------
// fp16 k/v gathers (half the L2 traffic). R12 phase structure.
#define CHUNK 12
__global__ void __launch_bounds__(128) fused_attn_kernel(
    const int* __restrict__ ei, const float* __restrict__ tfeat,
    const float* __restrict__ msg, float* __restrict__ out)
{
    const int n = blockIdx.x;
    const int tid = threadIdx.x;
    const int beg = g_off[n];
    const int deg = g_off[n + 1] - beg;

    if (deg == 0) {
        __half z = __float2half_rn(0.f);
#pragma unroll
        for (int l = 0; l < 3; l++) {
            size_t gi = (size_t)n * (HEADS * FDIM) + tid * 3 + l;
            g_ghi[gi] = z;        g_glo[gi] = z;
            g_ghi[gi + FDIM] = z; g_glo[gi + FDIM] = z;
        }
        return;
    }

    __shared__ __align__(16) float sq[DCH];
    __shared__ __align__(16) float sp[HEADS * FDIM];
    __shared__ __align__(16) float sea[CHUNK][FDIM];
    __shared__ float slog0[CHUNK], slog1[CHUNK];
    __shared__ float sw0[CHUNK], sw1[CHUNK];
    __shared__ int   ssrc[CHUNK];

    ((float4*)sq)[tid] = ((const float4*)(g_q + (size_t)n * DCH))[tid];
#pragma unroll
    for (int i = tid; i < (HEADS * FDIM) / 4; i += 128)
        ((float4*)sp)[i] = ((const float4*)(g_p + (size_t)n * (HEADS * FDIM)))[i];

    const int wid = tid >> 5, lane = tid & 31;

    float acc0 = 0.f, acc1 = 0.f, acc2 = 0.f, acc3 = 0.f;
    float ga0[3] = {0.f, 0.f, 0.f}, ga1[3] = {0.f, 0.f, 0.f};
    float rm0 = -1e30f, rm1 = -1e30f, den0 = 0.f, den1 = 0.f;

    for (int base = 0; base < deg; base += CHUNK) {
        const int cnt = min(CHUNK, deg - base);
        __syncthreads();

        // phase a: stage edge_attr chunk (warp per edge, strided)
        for (int j = wid; j < cnt; j += 4) {
            int e = g_perm[beg + base + j];
            if (lane == 0) ssrc[j] = ei[e];
            const float4* tr = (const float4*)(tfeat + (size_t)e * TDIM);
            const float4* mr = (const float4*)(msg + (size_t)e * MDIM);
            ((float4*)sea[j])[lane]      = tr[lane];
            ((float4*)sea[j])[32 + lane] = mr[lane];
            ((float4*)sea[j])[64 + lane] = mr[32 + lane];
        }
        __syncthreads();

        // phase b: logits (warp per edge), fp16 k gathers
        for (int j = wid; j < cnt; j += 4) {
            const uint2* kr = (const uint2*)(g_kh + (size_t)ssrc[j] * DCH);
            float a0 = 0.f, a1 = 0.f;
#pragma unroll
            for (int it = 0; it < 2; it++) {
                uint2 kv2 = kr[lane + 32 * it];
                float2 f0 = __half22float2(*(__half2*)&kv2.x);
                float2 f1 = __half22float2(*(__half2*)&kv2.y);
                float4 qv = ((const float4*)sq)[lane + 32 * it];
                a0 += f0.x * qv.x + f0.y * qv.y + f1.x * qv.z + f1.y * qv.w;
            }
#pragma unroll
            for (int it = 2; it < 4; it++) {
                uint2 kv2 = kr[lane + 32 * it];
                float2 f0 = __half22float2(*(__half2*)&kv2.x);
                float2 f1 = __half22float2(*(__half2*)&kv2.y);
                float4 qv = ((const float4*)sq)[lane + 32 * it];
                a1 += f0.x * qv.x + f0.y * qv.y + f1.x * qv.z + f1.y * qv.w;
            }
#pragma unroll
            for (int it = 0; it < 3; it++) {
                float4 ev = ((const float4*)sea[j])[lane + 32 * it];
                float4 p0 = ((const float4*)sp)[lane + 32 * it];
                float4 p1 = ((const float4*)sp)[96 + lane + 32 * it];
                a0 += ev.x * p0.x + ev.y * p0.y + ev.z * p0.z + ev.w * p0.w;
                a1 += ev.x * p1.x + ev.y * p1.y + ev.z * p1.z + ev.w * p1.w;
            }
#pragma unroll
            for (int o = 16; o; o >>= 1) {
                a0 += __shfl_xor_sync(0xffffffffu, a0, o);
                a1 += __shfl_xor_sync(0xffffffffu, a1, o);
            }
            if (lane == 0) {
                slog0[j] = a0 * 0.0625f;
                slog1[j] = a1 * 0.0625f;
            }
        }
        __syncthreads();

        // phase c: online-softmax rescale + chunk weights
        float cm0 = -1e30f, cm1 = -1e30f;
        for (int j = 0; j < cnt; j++) {
            cm0 = fmaxf(cm0, slog0[j]);
            cm1 = fmaxf(cm1, slog1[j]);
        }
        float nm0 = fmaxf(rm0, cm0), nm1 = fmaxf(rm1, cm1);
        float sc0 = expf(rm0 - nm0), sc1 = expf(rm1 - nm1);
        float scv = (tid < 64) ? sc0 : sc1;
        acc0 *= scv; acc1 *= scv; acc2 *= scv; acc3 *= scv;
#pragma unroll
        for (int l = 0; l < 3; l++) { ga0[l] *= sc0; ga1[l] *= sc1; }
        den0 *= sc0; den1 *= sc1;
        rm0 = nm0; rm1 = nm1;
        if (tid < cnt) {
            sw0[tid] = expf(slog0[tid] - nm0);
            sw1[tid] = expf(slog1[tid] - nm1);
        }
        __syncthreads();

        // phase d: accumulate v (fp16 gathers) and G from staged chunk
        for (int j = 0; j < cnt; j++) {
            float w0 = sw0[j], w1 = sw1[j];
            float wv = (tid < 64) ? w0 : w1;
            uint2 vv2 = *(const uint2*)(g_vh + (size_t)ssrc[j] * DCH + tid * 4);
            float2 va = __half22float2(*(__half2*)&vv2.x);
            float2 vb = __half22float2(*(__half2*)&vv2.y);
            acc0 += wv * va.x; acc1 += wv * va.y;
            acc2 += wv * vb.x; acc3 += wv * vb.y;
            const float* er = sea[j] + tid * 3;
            float e0 = er[0], e1 = er[1], e2 = er[2];
            ga0[0] += w0 * e0; ga0[1] += w0 * e1; ga0[2] += w0 * e2;
            ga1[0] += w1 * e0; ga1[1] += w1 * e1; ga1[2] += w1 * e2;
            den0 += w0; den1 += w1;
        }
    }

    float inv0 = 1.f / (den0 + 1e-16f);
    float inv1 = 1.f / (den1 + 1e-16f);
    float invv = (tid < 64) ? inv0 : inv1;

    float4* op = (float4*)(out + (size_t)n * DCH + tid * 4);
    float4 o = *op;
    o.x += acc0 * invv; o.y += acc1 * invv;
    o.z += acc2 * invv; o.w += acc3 * invv;
    *op = o;

#pragma unroll
    for (int l = 0; l < 3; l++) {
        size_t gi = (size_t)n * (HEADS * FDIM) + tid * 3 + l;
        float v0 = ga0[l] * inv0;
        float v1 = ga1[l] * inv1;
        __half h0 = __float2half_rn(v0);
        __half h1 = __float2half_rn(v1);
        g_ghi[gi] = h0;
        g_glo[gi] = __float2half_rn(v0 - __half2float(h0));
        g_ghi[gi + FDIM] = h1;
        g_glo[gi + FDIM] = __float2half_rn(v1 - __half2float(h1));
    }
}

// ---------------- launch ----------------
extern "C" void kernel_launch(void* const* d_in, const int* in_sizes, int n_in,
                              void* d_out, int out_size)
{
    const float* x     = (const float*)d_in[0];
    const int*   ei    = (const int*)d_in[2];
    const float* tfeat = (const float*)d_in[3];
    const float* msg   = (const float*)d_in[4];
    const float* Wq    = (const float*)d_in[5];
    const float* bq    = (const float*)d_in[6];
    const float* Wk    = (const float*)d_in[7];
    const float* bk    = (const float*)d_in[8];
    const float* Wv    = (const float*)d_in[9];
    const float* bv    = (const float*)d_in[10];
    const float* We    = (const float*)d_in[11];
    const float* Ws    = (const float*)d_in[12];
    const float* bs    = (const float*)d_in[13];
    float* out = (float*)d_out;

    // 1: conversions + pbias
    misc_prep<<<PB_X + PB_W + PB_WE + PB_PB, 256>>>(x, We, bq, Wq, Wk, Wv, Ws);
    // 2: WeT (fp32, for M)
    transpose_we_kernel<<<(HEADS * C_HEAD * FDIM + 255) / 256, 256>>>(We);
    // 3: M_h = Wq_h @ WeT_h  (written as single fp16 into g_w rows 2048+)
    dim3 gm(FDIM / 128, 4, HEADS);
    gemm_m_kernel<<<gm, 256>>>(Wq);
    // 4: tensor-core projection GEMM  <-- profiled slot
    dim3 gproj(NCAT / 128, (N_NODES + 127) / 128);
    mma_proj<<<gproj, 256>>>(bq, bk, bv, bs, out);
    // 5-8: CSR
    zero_deg_kernel<<<(N_NODES + 255) / 256, 256>>>();
    count_deg_kernel<<<(E_EDGES + 255) / 256, 256>>>(ei);
    scan_kernel<<<1, 1024>>>();
    scatter_perm_kernel<<<(E_EDGES + 255) / 256, 256>>>(ei);
    // 9: fused edge logits + online softmax + aggregation (fp16 k/v gathers)
    fused_attn_kernel<<<N_NODES, 128>>>(ei, tfeat, msg, out);
    // 10: out += G @ We  (mma.sync, 2-product split-fp16)
    dim3 gout(2 * HEADS, (N_NODES + 127) / 128);
    mma_out<<<gout, 256>>>(out);
}

// round 16
// speedup vs baseline: 1.2691x; 1.1373x over previous
#include <cuda_runtime.h>
#include <cuda_fp16.h>
#include <math.h>
#include <stdint.h>

#define N_NODES 10000
#define E_EDGES 160000
#define DCH 512
#define C_HEAD 256
#define HEADS 2
#define TDIM 128
#define MDIM 256
#define FDIM 384   // TDIM + MDIM
#define NCAT 2816  // 4*512 (q,k,v,skip) + 2*384 (p heads)

// ---------------- scratch (device globals) ----------------
__device__ float  g_q[N_NODES * DCH];
__device__ __half g_kh[N_NODES * DCH];                // fp16 k (written by mma_proj)
__device__ __half g_vh[N_NODES * DCH];                // fp16 v (written by mma_proj)
__device__ float  g_p[N_NODES * HEADS * FDIM];
__device__ float  g_WeT[HEADS * C_HEAD * FDIM];       // WeT[h][c][f] = We[f][h*C+c]
__device__ float  g_pbias[HEADS * FDIM];
__device__ int    g_deg[N_NODES];
__device__ int    g_cur[N_NODES];
__device__ int    g_off[N_NODES + 1];
__device__ int    g_perm[E_EDGES];
// fp16 operands (single precision level, no hi/lo split)
__device__ __half g_xh[N_NODES * DCH];
__device__ __half g_w[NCAT * DCH];                     // K-major: [n][k]
__device__ __half g_wekt[HEADS * C_HEAD * FDIM];       // [h][n][k]
__device__ __half g_gh[N_NODES * HEADS * FDIM];        // [n][h*384+f]

// ================= mma.sync helpers (fp16 in, fp32 accum) =================
__device__ __forceinline__ void mma_f16_acc(
    float c[4], uint32_t a0, uint32_t a1, uint32_t a2, uint32_t a3,
    uint32_t b0, uint32_t b1)
{
    asm volatile(
        "mma.sync.aligned.m16n8k16.row.col.f32.f16.f16.f32 "
        "{%0,%1,%2,%3}, {%4,%5,%6,%7}, {%8,%9}, {%0,%1,%2,%3};"
        : "+f"(c[0]), "+f"(c[1]), "+f"(c[2]), "+f"(c[3])
        : "r"(a0), "r"(a1), "r"(a2), "r"(a3), "r"(b0), "r"(b1));
}
__device__ __forceinline__ void ldm_x4(uint32_t& r0, uint32_t& r1,
                                       uint32_t& r2, uint32_t& r3, uint32_t a) {
    asm volatile("ldmatrix.sync.aligned.m8n8.x4.shared.b16 {%0,%1,%2,%3}, [%4];"
                 : "=r"(r0), "=r"(r1), "=r"(r2), "=r"(r3) : "r"(a));
}

#define LDK 24                       // 48B row stride: 16B-aligned, ldmatrix conflict-free
#define STG_ELEMS (128 * LDK)        // 3072 fp16 = 6144 B per array
#define AR_BYTES (STG_ELEMS * 2)
#define ST_BYTES (2 * AR_BYTES)      // A, B = 12288 B per stage

// ---------------- mma mainloop: 128x128 CTA tile, BK=16, double-buffered -------
// 256 threads, 8 warps, warp tile 32x64 (4m x 2n grid). Single-product fp16.
__device__ __forceinline__ void mma_mainloop(
    const __half* __restrict__ A, int lda, int m0, int Mrows,
    const __half* __restrict__ B, int ldb, int n0, int K,
    float cacc[2][8][4])
{
    __shared__ __align__(16) char smraw[2 * ST_BYTES];   // 24 KB static

    const int tid = threadIdx.x;
    const int row = tid >> 1;
    const int colh = (tid & 1) * 8;
    const int lane = tid & 31;
    const int wid = tid >> 5;
    const int wm = (wid & 3) * 32;
    const int wn = (wid >> 2) * 64;
    const int lr = lane & 7, seg = lane >> 3;

    const bool aOk = (m0 + row) < Mrows;
    const int arow = aOk ? (m0 + row) : 0;
    const __half* Ap = A + (size_t)arow * lda + colh;
    const __half* Bp = B + (size_t)(n0 + row) * ldb + colh;

    const uint32_t smBase = (uint32_t)__cvta_generic_to_shared(smraw);
    const uint32_t wrOff = (row * LDK + colh) * 2;

    const int nkt = K >> 4;

    uint32_t bOffP[4], aOffM[2];
#pragma unroll
    for (int p = 0; p < 4; p++)
        bOffP[p] = ((wn + (2 * p + (seg >> 1)) * 8 + lr) * LDK + (seg & 1) * 8) * 2;
#pragma unroll
    for (int mt = 0; mt < 2; mt++)
        aOffM[mt] = ((wm + mt * 16 + (seg & 1) * 8 + lr) * LDK + (seg >> 1) * 8) * 2;

    const uint4 z4 = make_uint4(0u, 0u, 0u, 0u);
    uint4 ra = aOk ? *(const uint4*)Ap : z4;
    uint4 rb = *(const uint4*)Bp;

    {
        char* b = smraw + wrOff;
        *(uint4*)(b + 0 * AR_BYTES) = ra;
        *(uint4*)(b + 1 * AR_BYTES) = rb;
    }
    __syncthreads();

    for (int kt = 0; kt < nkt; kt++) {
        const int s = kt & 1;
        if (kt + 1 < nkt) {
            const int ko = (kt + 1) * 16;
            ra = aOk ? *(const uint4*)(Ap + ko) : z4;
            rb = *(const uint4*)(Bp + ko);
        }

        const uint32_t sb = smBase + s * ST_BYTES;
        uint32_t bh[8][2];
#pragma unroll
        for (int p = 0; p < 4; p++)
            ldm_x4(bh[2 * p][0], bh[2 * p][1], bh[2 * p + 1][0], bh[2 * p + 1][1],
                   sb + 1 * AR_BYTES + bOffP[p]);
#pragma unroll
        for (int mt = 0; mt < 2; mt++) {
            uint32_t a0, a1, a2, a3;
            ldm_x4(a0, a1, a2, a3, sb + 0 * AR_BYTES + aOffM[mt]);
#pragma unroll
            for (int nt = 0; nt < 8; nt++)
                mma_f16_acc(cacc[mt][nt], a0, a1, a2, a3, bh[nt][0], bh[nt][1]);
        }

        if (kt + 1 < nkt) {
            char* b = smraw + (s ^ 1) * ST_BYTES + wrOff;
            *(uint4*)(b + 0 * AR_BYTES) = ra;
            *(uint4*)(b + 1 * AR_BYTES) = rb;
            __syncthreads();
        }
    }
}

// ---------------- kernel 1: fused projections q/k/v/skip/p ----------------
// q, skip, p written fp32; k, v written fp16.
__global__ void __launch_bounds__(256, 2) mma_proj(
    const float* __restrict__ bq, const float* __restrict__ bk,
    const float* __restrict__ bv, const float* __restrict__ bs,
    float* __restrict__ out)
{
    float cacc[2][8][4] = {};
    const int j = blockIdx.x;
    const int m0 = blockIdx.y * 128;
    mma_mainloop(g_xh, DCH, m0, N_NODES, g_w, DCH, j * 128, DCH, cacc);

    const int lane = threadIdx.x & 31, wid = threadIdx.x >> 5;
    const int wm = (wid & 3) * 32, wn = (wid >> 2) * 64;
    const int g = lane >> 2, t = lane & 3;

    float* dstf = nullptr; __half* dsth = nullptr;
    const float* bvec; int col0, ldc;
    if (j < 16) {
        int seg = j >> 2;
        if (seg == 0)      { dstf = g_q;  bvec = bq; }
        else if (seg == 1) { dsth = g_kh; bvec = bk; }
        else if (seg == 2) { dsth = g_vh; bvec = bv; }
        else               { dstf = out;  bvec = bs; }
        col0 = (j & 3) * 128; ldc = DCH;
    } else {
        dstf = g_p; bvec = g_pbias;
        col0 = (j - 16) * 128; ldc = HEADS * FDIM;
    }
#pragma unroll
    for (int mt = 0; mt < 2; mt++) {
#pragma unroll
        for (int nt = 0; nt < 8; nt++) {
            int gc = col0 + wn + nt * 8 + 2 * t;
            float b0v = bvec[gc], b1v = bvec[gc + 1];
            int r0 = m0 + wm + mt * 16 + g;
            if (r0 < N_NODES) {
                float vx = cacc[mt][nt][0] + b0v, vy = cacc[mt][nt][1] + b1v;
                if (dstf) *(float2*)&dstf[(size_t)r0 * ldc + gc] = make_float2(vx, vy);
                else      *(__half2*)&dsth[(size_t)r0 * ldc + gc] = __floats2half2_rn(vx, vy);
            }
            int r1 = r0 + 8;
            if (r1 < N_NODES) {
                float vx = cacc[mt][nt][2] + b0v, vy = cacc[mt][nt][3] + b1v;
                if (dstf) *(float2*)&dstf[(size_t)r1 * ldc + gc] = make_float2(vx, vy);
                else      *(__half2*)&dsth[(size_t)r1 * ldc + gc] = __floats2half2_rn(vx, vy);
            }
        }
    }
}

// ---------------- kernel 2: out += G @ We (per head) ----------------
__global__ void __launch_bounds__(256, 2) mma_out(float* __restrict__ out)
{
    float cacc[2][8][4] = {};
    const int j = blockIdx.x;
    const int h = j >> 1, jt = j & 1;
    const int m0 = blockIdx.y * 128;
    mma_mainloop(g_gh + h * FDIM, HEADS * FDIM, m0, N_NODES,
                 g_wekt + (size_t)h * C_HEAD * FDIM, FDIM, jt * 128, FDIM, cacc);

    const int lane = threadIdx.x & 31, wid = threadIdx.x >> 5;
    const int wm = (wid & 3) * 32, wn = (wid >> 2) * 64;
    const int g = lane >> 2, t = lane & 3;
    const int col0 = h * C_HEAD + jt * 128;

#pragma unroll
    for (int mt = 0; mt < 2; mt++) {
#pragma unroll
        for (int nt = 0; nt < 8; nt++) {
            int gc = col0 + wn + nt * 8 + 2 * t;
            int r0 = m0 + wm + mt * 16 + g;
            if (r0 < N_NODES) {
                float2* op = (float2*)&out[(size_t)r0 * DCH + gc];
                float2 v = *op;
                v.x += cacc[mt][nt][0]; v.y += cacc[mt][nt][1];
                *op = v;
            }
            int r1 = r0 + 8;
            if (r1 < N_NODES) {
                float2* op = (float2*)&out[(size_t)r1 * DCH + gc];
                float2 v = *op;
                v.x += cacc[mt][nt][2]; v.y += cacc[mt][nt][3];
                *op = v;
            }
        }
    }
}

// ---------------- fp32 GEMM tile (M = Wq @ WeT, writes single fp16 weights) ------
__device__ __forceinline__ void gemm_tile_w(
    const float* __restrict__ A, int lda,
    const float* __restrict__ B, int ldb,
    int K, int bm, int bn,
    __half* wdst, int wrow0,
    float As[2][16][136], float Bs[2][16][128])
{
    const int tid = threadIdx.x;
    const int tx = tid & 15, ty = tid >> 4;
    const int aRow = tid >> 2;
    const int aCol = (tid & 3) * 4;
    const int bRow = tid >> 4;
    const int bCol = (tid & 15) * 4;

    const float* Ap0 = A + (size_t)(bm + aRow) * lda + aCol;
    const float* Ap1 = A + (size_t)(bm + aRow + 64) * lda + aCol;
    const float* Bp0 = B + (size_t)bRow * ldb + bn + bCol;
    const float* Bp1 = Bp0 + 64;
    const int nkt = K >> 4;

    float4 a0r = *(const float4*)Ap0;
    float4 a1r = *(const float4*)Ap1;
    float4 b0r = *(const float4*)Bp0;
    float4 b1r = *(const float4*)Bp1;

    As[0][aCol + 0][aRow] = a0r.x; As[0][aCol + 1][aRow] = a0r.y;
    As[0][aCol + 2][aRow] = a0r.z; As[0][aCol + 3][aRow] = a0r.w;
    As[0][aCol + 0][aRow + 64] = a1r.x; As[0][aCol + 1][aRow + 64] = a1r.y;
    As[0][aCol + 2][aRow + 64] = a1r.z; As[0][aCol + 3][aRow + 64] = a1r.w;
    *(float4*)&Bs[0][bRow][bCol] = b0r;
    *(float4*)&Bs[0][bRow][bCol + 64] = b1r;
    __syncthreads();

    float acc[8][8];
#pragma unroll
    for (int i = 0; i < 8; i++)
#pragma unroll
        for (int jj = 0; jj < 8; jj++) acc[i][jj] = 0.f;

    for (int kt = 0; kt < nkt; kt++) {
        const int s = kt & 1;
        if (kt + 1 < nkt) {
            const int ko = (kt + 1) * 16;
            a0r = *(const float4*)(Ap0 + ko);
            a1r = *(const float4*)(Ap1 + ko);
            b0r = *(const float4*)(Bp0 + (size_t)ko * ldb);
            b1r = *(const float4*)(Bp1 + (size_t)ko * ldb);
        }
#pragma unroll
        for (int kk = 0; kk < 16; kk++) {
            float4 av0 = *(const float4*)&As[s][kk][ty * 8];
            float4 av1 = *(const float4*)&As[s][kk][ty * 8 + 4];
            float4 bv0 = *(const float4*)&Bs[s][kk][tx * 4];
            float4 bv1 = *(const float4*)&Bs[s][kk][tx * 4 + 64];
            float ar[8] = {av0.x, av0.y, av0.z, av0.w, av1.x, av1.y, av1.z, av1.w};
            float br[8] = {bv0.x, bv0.y, bv0.z, bv0.w, bv1.x, bv1.y, bv1.z, bv1.w};
#pragma unroll
            for (int i = 0; i < 8; i++)
#pragma unroll
                for (int jj = 0; jj < 8; jj++) acc[i][jj] += ar[i] * br[jj];
        }
        if (kt + 1 < nkt) {
            __syncthreads();
            const int s1 = s ^ 1;
            As[s1][aCol + 0][aRow] = a0r.x; As[s1][aCol + 1][aRow] = a0r.y;
            As[s1][aCol + 2][aRow] = a0r.z; As[s1][aCol + 3][aRow] = a0r.w;
            As[s1][aCol + 0][aRow + 64] = a1r.x; As[s1][aCol + 1][aRow + 64] = a1r.y;
            As[s1][aCol + 2][aRow + 64] = a1r.z; As[s1][aCol + 3][aRow + 64] = a1r.w;
            *(float4*)&Bs[s1][bRow][bCol] = b0r;
            *(float4*)&Bs[s1][bRow][bCol + 64] = b1r;
            __syncthreads();
        }
    }

#pragma unroll
    for (int i = 0; i < 8; i++) {
        int kk = bm + ty * 8 + i;
#pragma unroll
        for (int jj = 0; jj < 8; jj++) {
            int f = bn + ((jj < 4) ? (tx * 4 + jj) : (64 + tx * 4 + jj - 4));
            int n = wrow0 + f;
            wdst[(size_t)n * DCH + kk] = __float2half_rn(acc[i][jj]);
        }
    }
}

__global__ void __launch_bounds__(256) gemm_m_kernel(const float* __restrict__ Wq) {
    __shared__ __align__(16) float As[2][16][136];
    __shared__ __align__(16) float Bs[2][16][128];
    int h = blockIdx.z;
    gemm_tile_w(Wq + h * C_HEAD, DCH,
                g_WeT + (size_t)h * C_HEAD * FDIM, FDIM,
                C_HEAD, blockIdx.y * 128, blockIdx.x * 128,
                g_w, 4 * DCH + h * FDIM, As, Bs);
}

// ---------------- prep: conv x, conv W, conv WeKT, pbias --------
#define PB_X  20000
#define PB_W  4096
#define PB_WE 768
#define PB_PB 3
__global__ void misc_prep(const float* __restrict__ x, const float* __restrict__ We,
                          const float* __restrict__ bq,
                          const float* __restrict__ Wq, const float* __restrict__ Wk,
                          const float* __restrict__ Wv, const float* __restrict__ Ws)
{
    int b = blockIdx.x, t = threadIdx.x;
    if (b < PB_X) {
        int i = b * 256 + t;
        g_xh[i] = __float2half_rn(x[i]);
    } else if (b < PB_X + PB_W) {
        int idx = (b - PB_X) * 256 + t;
        int k = idx >> 11, n = idx & 2047;
        int seg = n >> 9, cc = n & 511;
        const float* W = (seg == 0) ? Wq : (seg == 1) ? Wk : (seg == 2) ? Wv : Ws;
        g_w[(size_t)n * DCH + k] = __float2half_rn(W[(size_t)k * DCH + cc]);
    } else if (b < PB_X + PB_W + PB_WE) {
        int idx = (b - PB_X - PB_W) * 256 + t;   // [h][n][k] with k fastest
        int h = idx / (C_HEAD * FDIM);
        int r = idx - h * (C_HEAD * FDIM);
        int n = r / FDIM, k = r - n * FDIM;
        g_wekt[idx] = __float2half_rn(We[(size_t)k * DCH + h * C_HEAD + n]);
    } else {
        int i = (b - PB_X - PB_W - PB_WE) * 256 + t;
        if (i < HEADS * FDIM) {
            int h = i / FDIM, f = i - h * FDIM;
            float s = 0.f;
            for (int c = 0; c < C_HEAD; c++)
                s += bq[h * C_HEAD + c] * We[(size_t)f * DCH + h * C_HEAD + c];
            g_pbias[i] = s;
        }
    }
}

// ---------------- We transpose ----------------
__global__ void transpose_we_kernel(const float* __restrict__ We) {
    int i = blockIdx.x * 256 + threadIdx.x;
    if (i < HEADS * C_HEAD * FDIM) {
        int h = i / (C_HEAD * FDIM);
        int r = i % (C_HEAD * FDIM);
        int c = r / FDIM;
        int f = r % FDIM;
        g_WeT[i] = We[(size_t)f * DCH + h * C_HEAD + c];
    }
}

// ---------------- CSR build ----------------
__global__ void zero_deg_kernel() {
    int i = blockIdx.x * 256 + threadIdx.x;
    if (i < N_NODES) g_deg[i] = 0;
}
__global__ void count_deg_kernel(const int* __restrict__ ei) {
    int i = blockIdx.x * 256 + threadIdx.x;
    if (i < E_EDGES) atomicAdd(&g_deg[ei[E_EDGES + i]], 1);
}
__global__ void __launch_bounds__(1024) scan_kernel() {
    __shared__ int part[1024];
    int tid = threadIdx.x;
    int base = tid * 10;
    int local[10];
    int s = 0;
#pragma unroll
    for (int j = 0; j < 10; j++) {
        int idx = base + j;
        int d = (idx < N_NODES) ? g_deg[idx] : 0;
        local[j] = d;
        s += d;
    }
    part[tid] = s;
    __syncthreads();
    for (int off = 1; off < 1024; off <<= 1) {
        int v = part[tid];
        int add = (tid >= off) ? part[tid - off] : 0;
        __syncthreads();
        part[tid] = v + add;
        __syncthreads();
    }
    int run = (tid > 0) ? part[tid - 1] : 0;
#pragma unroll
    for (int j = 0; j < 10; j++) {
        int idx = base + j;
        if (idx < N_NODES) {
            g_off[idx] = run;
            run += local[j];
            g_cur[idx] = 0;
        }
    }
    if (tid == 1023) g_off[N_NODES] = part[1023];
}
__global__ void scatter_perm_kernel(const int* __restrict__ ei) {
    int i = blockIdx.x * 256 + threadIdx.x;
    if (i < E_EDGES) {
        int d = ei[E_EDGES + i];
        int p = g_off[d] + atomicAdd(&g_cur[d], 1);
        g_perm[p] = i;
    }
}

// ---------------- fused edge logits + online softmax + aggregation ----------------
// fp16 k/v gathers. R12 phase structure. Single-fp16 G output.
#define CHUNK 12
__global__ void __launch_bounds__(128) fused_attn_kernel(
    const int* __restrict__ ei, const float* __restrict__ tfeat,
    const float* __restrict__ msg, float* __restrict__ out)
{
    const int n = blockIdx.x;
    const int tid = threadIdx.x;
    const int beg = g_off[n];
    const int deg = g_off[n + 1] - beg;

    if (deg == 0) {
        __half z = __float2half_rn(0.f);
#pragma unroll
        for (int l = 0; l < 3; l++) {
            size_t gi = (size_t)n * (HEADS * FDIM) + tid * 3 + l;
            g_gh[gi] = z;
            g_gh[gi + FDIM] = z;
        }
        return;
    }

    __shared__ __align__(16) float sq[DCH];
    __shared__ __align__(16) float sp[HEADS * FDIM];
    __shared__ __align__(16) float sea[CHUNK][FDIM];
    __shared__ float slog0[CHUNK], slog1[CHUNK];
    __shared__ float sw0[CHUNK], sw1[CHUNK];
    __shared__ int   ssrc[CHUNK];

    ((float4*)sq)[tid] = ((const float4*)(g_q + (size_t)n * DCH))[tid];
#pragma unroll
    for (int i = tid; i < (HEADS * FDIM) / 4; i += 128)
        ((float4*)sp)[i] = ((const float4*)(g_p + (size_t)n * (HEADS * FDIM)))[i];

    const int wid = tid >> 5, lane = tid & 31;

    float acc0 = 0.f, acc1 = 0.f, acc2 = 0.f, acc3 = 0.f;
    float ga0[3] = {0.f, 0.f, 0.f}, ga1[3] = {0.f, 0.f, 0.f};
    float rm0 = -1e30f, rm1 = -1e30f, den0 = 0.f, den1 = 0.f;

    for (int base = 0; base < deg; base += CHUNK) {
        const int cnt = min(CHUNK, deg - base);
        __syncthreads();

        // phase a: stage edge_attr chunk (warp per edge, strided)
        for (int j = wid; j < cnt; j += 4) {
            int e = g_perm[beg + base + j];
            if (lane == 0) ssrc[j] = ei[e];
            const float4* tr = (const float4*)(tfeat + (size_t)e * TDIM);
            const float4* mr = (const float4*)(msg + (size_t)e * MDIM);
            ((float4*)sea[j])[lane]      = tr[lane];
            ((float4*)sea[j])[32 + lane] = mr[lane];
            ((float4*)sea[j])[64 + lane] = mr[32 + lane];
        }
        __syncthreads();

        // phase b: logits (warp per edge), fp16 k gathers
        for (int j = wid; j < cnt; j += 4) {
            const uint2* kr = (const uint2*)(g_kh + (size_t)ssrc[j] * DCH);
            float a0 = 0.f, a1 = 0.f;
#pragma unroll
            for (int it = 0; it < 2; it++) {
                uint2 kv2 = kr[lane + 32 * it];
                float2 f0 = __half22float2(*(__half2*)&kv2.x);
                float2 f1 = __half22float2(*(__half2*)&kv2.y);
                float4 qv = ((const float4*)sq)[lane + 32 * it];
                a0 += f0.x * qv.x + f0.y * qv.y + f1.x * qv.z + f1.y * qv.w;
            }
#pragma unroll
            for (int it = 2; it < 4; it++) {
                uint2 kv2 = kr[lane + 32 * it];
                float2 f0 = __half22float2(*(__half2*)&kv2.x);
                float2 f1 = __half22float2(*(__half2*)&kv2.y);
                float4 qv = ((const float4*)sq)[lane + 32 * it];
                a1 += f0.x * qv.x + f0.y * qv.y + f1.x * qv.z + f1.y * qv.w;
            }
#pragma unroll
            for (int it = 0; it < 3; it++) {
                float4 ev = ((const float4*)sea[j])[lane + 32 * it];
                float4 p0 = ((const float4*)sp)[lane + 32 * it];
                float4 p1 = ((const float4*)sp)[96 + lane + 32 * it];
                a0 += ev.x * p0.x + ev.y * p0.y + ev.z * p0.z + ev.w * p0.w;
                a1 += ev.x * p1.x + ev.y * p1.y + ev.z * p1.z + ev.w * p1.w;
            }
#pragma unroll
            for (int o = 16; o; o >>= 1) {
                a0 += __shfl_xor_sync(0xffffffffu, a0, o);
                a1 += __shfl_xor_sync(0xffffffffu, a1, o);
            }
            if (lane == 0) {
                slog0[j] = a0 * 0.0625f;
                slog1[j] = a1 * 0.0625f;
            }
        }
        __syncthreads();

        // phase c: online-softmax rescale + chunk weights
        float cm0 = -1e30f, cm1 = -1e30f;
        for (int j = 0; j < cnt; j++) {
            cm0 = fmaxf(cm0, slog0[j]);
            cm1 = fmaxf(cm1, slog1[j]);
        }
        float nm0 = fmaxf(rm0, cm0), nm1 = fmaxf(rm1, cm1);
        float sc0 = expf(rm0 - nm0), sc1 = expf(rm1 - nm1);
        float scv = (tid < 64) ? sc0 : sc1;
        acc0 *= scv; acc1 *= scv; acc2 *= scv; acc3 *= scv;
#pragma unroll
        for (int l = 0; l < 3; l++) { ga0[l] *= sc0; ga1[l] *= sc1; }
        den0 *= sc0; den1 *= sc1;
        rm0 = nm0; rm1 = nm1;
        if (tid < cnt) {
            sw0[tid] = expf(slog0[tid] - nm0);
            sw1[tid] = expf(slog1[tid] - nm1);
        }
        __syncthreads();

        // phase d: accumulate v (fp16 gathers) and G from staged chunk
        for (int j = 0; j < cnt; j++) {
            float w0 = sw0[j], w1 = sw1[j];
            float wv = (tid < 64) ? w0 : w1;
            uint2 vv2 = *(const uint2*)(g_vh + (size_t)ssrc[j] * DCH + tid * 4);
            float2 va = __half22float2(*(__half2*)&vv2.x);
            float2 vb = __half22float2(*(__half2*)&vv2.y);
            acc0 += wv * va.x; acc1 += wv * va.y;
            acc2 += wv * vb.x; acc3 += wv * vb.y;
            const float* er = sea[j] + tid * 3;
            float e0 = er[0], e1 = er[1], e2 = er[2];
            ga0[0] += w0 * e0; ga0[1] += w0 * e1; ga0[2] += w0 * e2;
            ga1[0] += w1 * e0; ga1[1] += w1 * e1; ga1[2] += w1 * e2;
            den0 += w0; den1 += w1;
        }
    }

    float inv0 = 1.f / (den0 + 1e-16f);
    float inv1 = 1.f / (den1 + 1e-16f);
    float invv = (tid < 64) ? inv0 : inv1;

    float4* op = (float4*)(out + (size_t)n * DCH + tid * 4);
    float4 o = *op;
    o.x += acc0 * invv; o.y += acc1 * invv;
    o.z += acc2 * invv; o.w += acc3 * invv;
    *op = o;

#pragma unroll
    for (int l = 0; l < 3; l++) {
        size_t gi = (size_t)n * (HEADS * FDIM) + tid * 3 + l;
        g_gh[gi]        = __float2half_rn(ga0[l] * inv0);
        g_gh[gi + FDIM] = __float2half_rn(ga1[l] * inv1);
    }
}

// ---------------- launch ----------------
extern "C" void kernel_launch(void* const* d_in, const int* in_sizes, int n_in,
                              void* d_out, int out_size)
{
    const float* x     = (const float*)d_in[0];
    const int*   ei    = (const int*)d_in[2];
    const float* tfeat = (const float*)d_in[3];
    const float* msg   = (const float*)d_in[4];
    const float* Wq    = (const float*)d_in[5];
    const float* bq    = (const float*)d_in[6];
    const float* Wk    = (const float*)d_in[7];
    const float* bk    = (const float*)d_in[8];
    const float* Wv    = (const float*)d_in[9];
    const float* bv    = (const float*)d_in[10];
    const float* We    = (const float*)d_in[11];
    const float* Ws    = (const float*)d_in[12];
    const float* bs    = (const float*)d_in[13];
    float* out = (float*)d_out;

    // 1: conversions + pbias
    misc_prep<<<PB_X + PB_W + PB_WE + PB_PB, 256>>>(x, We, bq, Wq, Wk, Wv, Ws);
    // 2: WeT (fp32, for M)
    transpose_we_kernel<<<(HEADS * C_HEAD * FDIM + 255) / 256, 256>>>(We);
    // 3: M_h = Wq_h @ WeT_h  (written as fp16 into g_w rows 2048+)
    dim3 gm(FDIM / 128, 4, HEADS);
    gemm_m_kernel<<<gm, 256>>>(Wq);
    // 4: tensor-core projection GEMM  <-- profiled slot
    dim3 gproj(NCAT / 128, (N_NODES + 127) / 128);
    mma_proj<<<gproj, 256>>>(bq, bk, bv, bs, out);
    // 5-8: CSR
    zero_deg_kernel<<<(N_NODES + 255) / 256, 256>>>();
    count_deg_kernel<<<(E_EDGES + 255) / 256, 256>>>(ei);
    scan_kernel<<<1, 1024>>>();
    scatter_perm_kernel<<<(E_EDGES + 255) / 256, 256>>>(ei);
    // 9: fused edge logits + online softmax + aggregation
    fused_attn_kernel<<<N_NODES, 128>>>(ei, tfeat, msg, out);
    // 10: out += G @ We  (mma.sync, single fp16)
    dim3 gout(2 * HEADS, (N_NODES + 127) / 128);
    mma_out<<<gout, 256>>>(out);
}